// round 1
// baseline (speedup 1.0000x reference)
#include <cuda_runtime.h>
#include <cstdint>

#define Bsz   32
#define Cdim  128
#define Hdim  112
#define Wdim  112
#define Mwin  7
#define Nwin  49          // M*M
#define NH    16          // H/M
#define NWIMG 256         // NH*NH windows per image
#define NWTOT 8192        // Bsz*NWIMG
#define HEADS 4
#define DHEAD 32
#define SHIFT 3

// row stride (padded) for 128-wide smem matrices
#define RS 132
// S matrix row stride
#define SRS 52

// ---------------- scratch (device globals; no allocation) ----------------
__device__ float g_win [(size_t)NWTOT * Nwin * Cdim];   // ~205 MB
__device__ float g_owin[(size_t)NWTOT * Nwin * Cdim];   // ~205 MB
__device__ float g_qkv_wt[128 * 384];                   // [c][j]
__device__ float g_proj_wt[128 * 128];                  // [c][j]
__device__ float g_bias[HEADS * Nwin * Nwin];           // [h][n][m]

// ---------------- K0: weight transpose + bias gather ----------------
__global__ void prep_kernel(const float* __restrict__ qkv_w,
                            const float* __restrict__ proj_w,
                            const float* __restrict__ bias_table,
                            const int*   __restrict__ rel_index) {
    int i = blockIdx.x * blockDim.x + threadIdx.x;
    if (i < 384 * 128) {
        int j = i / 128, c = i % 128;
        g_qkv_wt[c * 384 + j] = qkv_w[i];
    } else if (i < 384 * 128 + 128 * 128) {
        int t = i - 384 * 128;
        int j = t / 128, c = t % 128;
        g_proj_wt[c * 128 + j] = proj_w[t];
    } else if (i < 384 * 128 + 128 * 128 + HEADS * Nwin * Nwin) {
        int t = i - (384 * 128 + 128 * 128);
        int hd = t / (Nwin * Nwin), nm = t % (Nwin * Nwin);
        g_bias[t] = bias_table[rel_index[nm] * HEADS + hd];
    }
}

// ---------------- K1: LayerNorm + shift + window partition ----------------
// grid: (112 h, 2 halves of W, 32 b), block 256
__global__ void ln_window_kernel(const float* __restrict__ x,
                                 const float* __restrict__ nw,
                                 const float* __restrict__ nb) {
    __shared__ float s[56 * RS];
    int h = blockIdx.x, half = blockIdx.y, b = blockIdx.z;
    int w0 = half * 56;
    int tid = threadIdx.x;

    const float* xp = x + (size_t)b * Cdim * (Hdim * Wdim) + (size_t)h * Wdim + w0;
    // coalesced load: per c, 56 contiguous w
    for (int e = tid; e < 56 * 128; e += 256) {
        int c = e / 56, w = e % 56;
        s[w * RS + c] = xp[(size_t)c * (Hdim * Wdim) + w];
    }
    __syncthreads();

    int warp = tid >> 5, lane = tid & 31;
    for (int wl = warp; wl < 56; wl += 8) {
        float4 v = *(const float4*)&s[wl * RS + lane * 4];
        float sum = v.x + v.y + v.z + v.w;
        float sq  = v.x * v.x + v.y * v.y + v.z * v.z + v.w * v.w;
        #pragma unroll
        for (int o = 16; o > 0; o >>= 1) {
            sum += __shfl_xor_sync(0xffffffff, sum, o);
            sq  += __shfl_xor_sync(0xffffffff, sq,  o);
        }
        float mu  = sum * (1.0f / 128.0f);
        float var = sq * (1.0f / 128.0f) - mu * mu;
        float inv = rsqrtf(var + 1e-5f);

        int c0 = lane * 4;
        float4 g  = *(const float4*)&nw[c0];
        float4 be = *(const float4*)&nb[c0];
        float4 o;
        o.x = (v.x - mu) * inv * g.x + be.x;
        o.y = (v.y - mu) * inv * g.y + be.y;
        o.z = (v.z - mu) * inv * g.z + be.z;
        o.w = (v.w - mu) * inv * g.w + be.w;

        // destination after roll(-SHIFT): dest = src - SHIFT (mod)
        int ws = w0 + wl;
        int hd = h - SHIFT;  if (hd < 0) hd += Hdim;
        int wd = ws - SHIFT; if (wd < 0) wd += Wdim;
        int wi = b * NWIMG + (hd / Mwin) * NH + (wd / Mwin);
        int n  = (hd % Mwin) * Mwin + (wd % Mwin);
        *(float4*)&g_win[((size_t)wi * Nwin + n) * Cdim + c0] = o;
    }
}

// ---------------- K2: fused window attention ----------------
// one CTA per window, 256 threads, dynamic smem
// smem: sO(X) | sQ | sK | sV : 49x128 pad RS each; sS: 4 x 49 x SRS (+pad)
#define SOFF_Q (Nwin * RS)          // 6468
#define SOFF_K (2 * Nwin * RS)
#define SOFF_V (3 * Nwin * RS)
#define SOFF_S (4 * Nwin * RS)
#define SS_PAD 10752                 // 4*49*52 = 10192, padded for overflow-row reads
#define SMEM_FLOATS (4 * Nwin * RS + SS_PAD)

__global__ void attn_kernel(const float* __restrict__ qkv_b,
                            const float* __restrict__ proj_b,
                            const float* __restrict__ attn_mask) {
    extern __shared__ float sm[];
    float* sO = sm;          // holds X first, then attention output
    float* sQ = sm + SOFF_Q;
    float* sK = sm + SOFF_K;
    float* sV = sm + SOFF_V;
    float* sS = sm + SOFF_S;

    int wi   = blockIdx.x;
    int wimg = wi & (NWIMG - 1);
    int tid  = threadIdx.x;

    // load X (49 x 128), coalesced
    {
        const float* win = g_win + (size_t)wi * Nwin * Cdim;
        for (int e = tid; e < Nwin * Cdim; e += 256) {
            int n = e >> 7, c = e & 127;
            sO[n * RS + c] = win[e];
        }
    }
    __syncthreads();

    int ty = tid >> 4, tx = tid & 15;     // 16x16 thread grid

    // ---- QKV GEMM: [49x128] x [128x384] in 3 passes of 128 cols ----
    const float qscale = 0.17677669529663687f;   // 1/sqrt(32)
    #pragma unroll 1
    for (int pass = 0; pass < 3; ++pass) {
        float acc[4][8];
        #pragma unroll
        for (int r = 0; r < 4; ++r)
            #pragma unroll
            for (int jj = 0; jj < 8; ++jj) acc[r][jj] = 0.f;

        const float* Wt = g_qkv_wt + pass * 128 + tx * 8;
        #pragma unroll 4
        for (int c = 0; c < 128; ++c) {
            float4 w0 = *(const float4*)(Wt + c * 384);
            float4 w1 = *(const float4*)(Wt + c * 384 + 4);
            #pragma unroll
            for (int r = 0; r < 4; ++r) {
                float xv = sO[(ty + r * 16) * RS + c];   // overflow rows read junk, never stored
                acc[r][0] += xv * w0.x; acc[r][1] += xv * w0.y;
                acc[r][2] += xv * w0.z; acc[r][3] += xv * w0.w;
                acc[r][4] += xv * w1.x; acc[r][5] += xv * w1.y;
                acc[r][6] += xv * w1.z; acc[r][7] += xv * w1.w;
            }
        }
        float* dst = (pass == 0) ? sQ : (pass == 1) ? sK : sV;
        float scale = (pass == 0) ? qscale : 1.0f;
        #pragma unroll
        for (int r = 0; r < 4; ++r) {
            int n = ty + r * 16;
            if (n < Nwin) {
                #pragma unroll
                for (int jj = 0; jj < 8; ++jj) {
                    int j = tx * 8 + jj;
                    dst[n * RS + j] = (acc[r][jj] + qkv_b[pass * 128 + j]) * scale;
                }
            }
        }
    }
    __syncthreads();

    // ---- S = Q K^T + bias + mask, per head ----
    #pragma unroll 1
    for (int hd = 0; hd < HEADS; ++hd) {
        float acc[4][4];
        #pragma unroll
        for (int r = 0; r < 4; ++r)
            #pragma unroll
            for (int s2 = 0; s2 < 4; ++s2) acc[r][s2] = 0.f;
        const float* Qh = sQ + hd * DHEAD;
        const float* Kh = sK + hd * DHEAD;
        #pragma unroll 4
        for (int c = 0; c < DHEAD; ++c) {
            float qv[4], kv[4];
            #pragma unroll
            for (int r = 0; r < 4; ++r)  qv[r]  = Qh[(ty + r * 16) * RS + c];
            #pragma unroll
            for (int s2 = 0; s2 < 4; ++s2) kv[s2] = Kh[(tx + s2 * 16) * RS + c];
            #pragma unroll
            for (int r = 0; r < 4; ++r)
                #pragma unroll
                for (int s2 = 0; s2 < 4; ++s2) acc[r][s2] += qv[r] * kv[s2];
        }
        #pragma unroll
        for (int r = 0; r < 4; ++r) {
            int n = ty + r * 16;
            if (n < Nwin) {
                #pragma unroll
                for (int s2 = 0; s2 < 4; ++s2) {
                    int m = tx + s2 * 16;
                    if (m < Nwin) {
                        sS[hd * (Nwin * SRS) + n * SRS + m] =
                            acc[r][s2] + g_bias[hd * (Nwin * Nwin) + n * Nwin + m]
                                       + attn_mask[((size_t)wimg * Nwin + n) * Nwin + m];
                    }
                }
            }
        }
    }
    __syncthreads();

    // ---- softmax over rows (4 heads x 49 rows = 196 rows) ----
    {
        int warp = tid >> 5, lane = tid & 31;
        for (int rid = warp; rid < HEADS * Nwin; rid += 8) {
            int hd = rid / Nwin, n = rid % Nwin;
            float* row = sS + hd * (Nwin * SRS) + n * SRS;
            float v0 = row[lane];
            float v1 = (lane + 32 < Nwin) ? row[lane + 32] : -1e30f;
            float mx = fmaxf(v0, v1);
            #pragma unroll
            for (int o = 16; o > 0; o >>= 1)
                mx = fmaxf(mx, __shfl_xor_sync(0xffffffff, mx, o));
            float e0 = __expf(v0 - mx);
            float e1 = (lane + 32 < Nwin) ? __expf(v1 - mx) : 0.f;
            float sum = e0 + e1;
            #pragma unroll
            for (int o = 16; o > 0; o >>= 1)
                sum += __shfl_xor_sync(0xffffffff, sum, o);
            float invs = 1.0f / sum;
            row[lane] = e0 * invs;
            if (lane + 32 < Nwin) row[lane + 32] = e1 * invs;
        }
    }
    __syncthreads();

    // ---- O = P V (per head), into sO[n][hd*32+dd] ----
    {
        int tx2 = tid & 31, ty2 = tid >> 5;   // dd, row-group
        #pragma unroll 1
        for (int hd = 0; hd < HEADS; ++hd) {
            float acc[7];
            #pragma unroll
            for (int k = 0; k < 7; ++k) acc[k] = 0.f;
            const float* P  = sS + hd * (Nwin * SRS);
            const float* Vh = sV + hd * DHEAD + tx2;
            #pragma unroll 7
            for (int m = 0; m < Nwin; ++m) {
                float vv = Vh[m * RS];
                #pragma unroll
                for (int k = 0; k < 7; ++k)
                    acc[k] += P[(ty2 + 8 * k) * SRS + m] * vv;   // padded sS covers overflow rows
            }
            #pragma unroll
            for (int k = 0; k < 7; ++k) {
                int n = ty2 + 8 * k;
                if (n < Nwin) sO[n * RS + hd * DHEAD + tx2] = acc[k];
            }
        }
    }
    __syncthreads();

    // ---- proj: [49x128] x [128x128], write g_owin ----
    {
        float acc[4][8];
        #pragma unroll
        for (int r = 0; r < 4; ++r)
            #pragma unroll
            for (int jj = 0; jj < 8; ++jj) acc[r][jj] = 0.f;
        const float* Wt = g_proj_wt + tx * 8;
        #pragma unroll 4
        for (int c = 0; c < 128; ++c) {
            float4 w0 = *(const float4*)(Wt + c * 128);
            float4 w1 = *(const float4*)(Wt + c * 128 + 4);
            #pragma unroll
            for (int r = 0; r < 4; ++r) {
                float xv = sO[(ty + r * 16) * RS + c];
                acc[r][0] += xv * w0.x; acc[r][1] += xv * w0.y;
                acc[r][2] += xv * w0.z; acc[r][3] += xv * w0.w;
                acc[r][4] += xv * w1.x; acc[r][5] += xv * w1.y;
                acc[r][6] += xv * w1.z; acc[r][7] += xv * w1.w;
            }
        }
        float4 pb0 = *(const float4*)(proj_b + tx * 8);
        float4 pb1 = *(const float4*)(proj_b + tx * 8 + 4);
        #pragma unroll
        for (int r = 0; r < 4; ++r) {
            int n = ty + r * 16;
            if (n < Nwin) {
                float4 o0, o1;
                o0.x = acc[r][0] + pb0.x; o0.y = acc[r][1] + pb0.y;
                o0.z = acc[r][2] + pb0.z; o0.w = acc[r][3] + pb0.w;
                o1.x = acc[r][4] + pb1.x; o1.y = acc[r][5] + pb1.y;
                o1.z = acc[r][6] + pb1.z; o1.w = acc[r][7] + pb1.w;
                float* dst = g_owin + ((size_t)wi * Nwin + n) * Cdim + tx * 8;
                *(float4*)dst = o0;
                *(float4*)(dst + 4) = o1;
            }
        }
    }
}

// ---------------- K3: window reverse + unshift + residual + NCHW write ----------------
// grid: (112 h, 2 halves, 32 b), block 256
__global__ void reverse_kernel(const float* __restrict__ x,
                               float* __restrict__ out) {
    __shared__ float s[128 * 57];
    int h = blockIdx.x, half = blockIdx.y, b = blockIdx.z;
    int w0 = half * 56;
    int tid = threadIdx.x;

    int h2 = h - SHIFT; if (h2 < 0) h2 += Hdim;     // source row in pre-roll layout
    int whh = h2 / Mwin, rr = h2 % Mwin;

    for (int e = tid; e < 56 * 128; e += 256) {
        int wl = e >> 7, c = e & 127;
        int w = w0 + wl;
        int w2 = w - SHIFT; if (w2 < 0) w2 += Wdim;
        int wi = b * NWIMG + whh * NH + (w2 / Mwin);
        int n  = rr * Mwin + (w2 % Mwin);
        s[c * 57 + wl] = g_owin[((size_t)wi * Nwin + n) * Cdim + c];
    }
    __syncthreads();

    size_t base = (size_t)b * Cdim * (Hdim * Wdim) + (size_t)h * Wdim + w0;
    for (int e = tid; e < 128 * 56; e += 256) {
        int c = e / 56, wl = e % 56;
        size_t gi = base + (size_t)c * (Hdim * Wdim) + wl;
        out[gi] = x[gi] + s[c * 57 + wl];
    }
}

// ---------------- launch ----------------
extern "C" void kernel_launch(void* const* d_in, const int* in_sizes, int n_in,
                              void* d_out, int out_size) {
    const float* x          = (const float*)d_in[0];
    const float* norm_w     = (const float*)d_in[1];
    const float* norm_b     = (const float*)d_in[2];
    const float* qkv_w      = (const float*)d_in[3];
    const float* qkv_b      = (const float*)d_in[4];
    const float* proj_w     = (const float*)d_in[5];
    const float* proj_b     = (const float*)d_in[6];
    const float* bias_table = (const float*)d_in[7];
    const int*   rel_index  = (const int*)  d_in[8];
    const float* attn_mask  = (const float*)d_in[9];
    float* out = (float*)d_out;

    static const int smem_bytes = SMEM_FLOATS * (int)sizeof(float);  // ~146 KB
    cudaFuncSetAttribute(attn_kernel, cudaFuncAttributeMaxDynamicSharedMemorySize, smem_bytes);

    int prep_total = 384 * 128 + 128 * 128 + HEADS * Nwin * Nwin;
    prep_kernel<<<(prep_total + 255) / 256, 256>>>(qkv_w, proj_w, bias_table, rel_index);
    ln_window_kernel<<<dim3(Hdim, 2, Bsz), 256>>>(x, norm_w, norm_b);
    attn_kernel<<<NWTOT, 256, smem_bytes>>>(qkv_b, proj_b, attn_mask);
    reverse_kernel<<<dim3(Hdim, 2, Bsz), 256>>>(x, out);
}

// round 3
// speedup vs baseline: 3.8215x; 3.8215x over previous
#include <cuda_runtime.h>
#include <cuda_bf16.h>
#include <cstdint>

#define Bsz   32
#define Cdim  128
#define Hdim  112
#define Wdim  112
#define Mwin  7
#define Nwin  49
#define NHw   16
#define NWIMG 256
#define NWTOT 8192
#define HEADS 4
#define DHEAD 32
#define SHIFT 3
#define NTOK  (NWTOT * Nwin)          // 401408
#define QSCALE 0.17677669529663687f   // 1/sqrt(32)

// ---------------- scratch (device globals; no allocation) ----------------
__device__ __nv_bfloat16 g_win [(size_t)NTOK * 128];   // LN+shifted tokens (bf16)
__device__ __nv_bfloat16 g_qkv [(size_t)NTOK * 384];   // QKV (bf16, Q pre-scaled)
__device__ __nv_bfloat16 g_attn[(size_t)NTOK * 128];   // attention output (bf16)
__device__ float         g_owin[(size_t)NTOK * 128];   // proj output (fp32)
__device__ __nv_bfloat16 g_wqkv [384 * 128];           // bf16 weights [j][k]
__device__ __nv_bfloat16 g_wproj[128 * 128];
__device__ float         g_bias [HEADS * Nwin * Nwin];

// ---------------- helpers ----------------
__device__ __forceinline__ uint32_t smem_u32(const void* p) {
    uint32_t a;
    asm("{ .reg .u64 t; cvta.to.shared.u64 t, %1; cvt.u32.u64 %0, t; }" : "=r"(a) : "l"(p));
    return a;
}
__device__ __forceinline__ void ldm_x4(uint32_t r[4], uint32_t addr) {
    asm volatile("ldmatrix.sync.aligned.m8n8.x4.shared.b16 {%0,%1,%2,%3}, [%4];"
        : "=r"(r[0]), "=r"(r[1]), "=r"(r[2]), "=r"(r[3]) : "r"(addr));
}
__device__ __forceinline__ void mma_bf16(float c[4], const uint32_t a[4],
                                         uint32_t b0, uint32_t b1) {
    asm volatile("mma.sync.aligned.m16n8k16.row.col.f32.bf16.bf16.f32 "
        "{%0,%1,%2,%3}, {%4,%5,%6,%7}, {%8,%9}, {%0,%1,%2,%3};"
        : "+f"(c[0]), "+f"(c[1]), "+f"(c[2]), "+f"(c[3])
        : "r"(a[0]), "r"(a[1]), "r"(a[2]), "r"(a[3]), "r"(b0), "r"(b1));
}

#define LDAB 272          // smem tile row stride in bytes (136 bf16)
#define TILE_B 34816      // 128 * 272

// ---------------- K0: weight bf16 conversion + bias gather ----------------
__global__ void prep_kernel(const float* __restrict__ qkv_w,
                            const float* __restrict__ proj_w,
                            const float* __restrict__ bias_table,
                            const int*   __restrict__ rel_index) {
    int i = blockIdx.x * blockDim.x + threadIdx.x;
    if (i < 384 * 128) {
        g_wqkv[i] = __float2bfloat16_rn(qkv_w[i]);
    } else if (i < 384 * 128 + 128 * 128) {
        int t = i - 384 * 128;
        g_wproj[t] = __float2bfloat16_rn(proj_w[t]);
    } else if (i < 384 * 128 + 128 * 128 + HEADS * Nwin * Nwin) {
        int t = i - (384 * 128 + 128 * 128);
        int hd = t / (Nwin * Nwin), nm = t % (Nwin * Nwin);
        g_bias[t] = bias_table[rel_index[nm] * HEADS + hd];
    }
}

// ---------------- K1: LayerNorm + shift + window partition (bf16 out) ----------------
#define RS 132
__global__ void ln_window_kernel(const float* __restrict__ x,
                                 const float* __restrict__ nw,
                                 const float* __restrict__ nb) {
    __shared__ float s[56 * RS];
    int h = blockIdx.x, half = blockIdx.y, b = blockIdx.z;
    int w0 = half * 56;
    int tid = threadIdx.x;

    const float* xp = x + (size_t)b * Cdim * (Hdim * Wdim) + (size_t)h * Wdim + w0;
    for (int e = tid; e < 56 * 128; e += 256) {
        int c = e / 56, w = e % 56;
        s[w * RS + c] = xp[(size_t)c * (Hdim * Wdim) + w];
    }
    __syncthreads();

    int warp = tid >> 5, lane = tid & 31;
    for (int wl = warp; wl < 56; wl += 8) {
        float4 v = *(const float4*)&s[wl * RS + lane * 4];
        float sum = v.x + v.y + v.z + v.w;
        float sq  = v.x * v.x + v.y * v.y + v.z * v.z + v.w * v.w;
        #pragma unroll
        for (int o = 16; o > 0; o >>= 1) {
            sum += __shfl_xor_sync(0xffffffff, sum, o);
            sq  += __shfl_xor_sync(0xffffffff, sq,  o);
        }
        float mu  = sum * (1.0f / 128.0f);
        float var = sq * (1.0f / 128.0f) - mu * mu;
        float inv = rsqrtf(var + 1e-5f);

        int c0 = lane * 4;
        float4 g  = *(const float4*)&nw[c0];
        float4 be = *(const float4*)&nb[c0];
        __align__(8) __nv_bfloat162 o2[2];
        o2[0] = __floats2bfloat162_rn((v.x - mu) * inv * g.x + be.x,
                                      (v.y - mu) * inv * g.y + be.y);
        o2[1] = __floats2bfloat162_rn((v.z - mu) * inv * g.z + be.z,
                                      (v.w - mu) * inv * g.w + be.w);

        int ws = w0 + wl;
        int hd = h - SHIFT;  if (hd < 0) hd += Hdim;
        int wd = ws - SHIFT; if (wd < 0) wd += Wdim;
        int wi = b * NWIMG + (hd / Mwin) * NHw + (wd / Mwin);
        int n  = (hd % Mwin) * Mwin + (wd % Mwin);
        *(uint2*)&g_win[((size_t)wi * Nwin + n) * 128 + c0] = *(uint2*)o2;
    }
}

// ---------------- K2: QKV GEMM (mma.sync bf16) ----------------
// CTA: 128 tokens x 384 cols, K=128. smem: A | B | Cstage(bf16), 102 KB -> 2 CTAs/SM
#define GQ_SMEM (3 * TILE_B)
__global__ __launch_bounds__(256, 2) void gemm_qkv_kernel(const float* __restrict__ qkv_b) {
    extern __shared__ __align__(16) char sm[];
    char* sA = sm;
    char* sB = sm + TILE_B;
    char* sC = sm + 2 * TILE_B;

    int tid = threadIdx.x, wid = tid >> 5, lane = tid & 31;
    int warp_m = wid >> 2, warp_n = wid & 3;

    const __nv_bfloat16* A = g_win + (size_t)blockIdx.x * (128 * 128);
    for (int e = tid; e < 2048; e += 256) {
        int r = e >> 4, j = e & 15;
        *(uint4*)(sA + r * LDAB + j * 16) = *(const uint4*)(A + r * 128 + j * 8);
    }
    for (int e = tid; e < 2048; e += 256) {
        int r = e >> 4, j = e & 15;
        *(uint4*)(sB + r * LDAB + j * 16) = *(const uint4*)(g_wqkv + r * 128 + j * 8);
    }
    __syncthreads();

    uint32_t pA = smem_u32(sA) + (uint32_t)((warp_m * 64 + (lane & 15)) * LDAB + ((lane >> 4) << 4));
    uint32_t pB = smem_u32(sB) + (uint32_t)((warp_n * 32 + (lane & 15)) * LDAB + ((lane >> 4) << 4));
    size_t row0 = (size_t)blockIdx.x * 128;
    int g = lane >> 2, tg = lane & 3;

    #pragma unroll 1
    for (int jb = 0; jb < 3; ++jb) {
        float c[4][4][4];
        #pragma unroll
        for (int mt = 0; mt < 4; ++mt)
            #pragma unroll
            for (int nt = 0; nt < 4; ++nt)
                #pragma unroll
                for (int q = 0; q < 4; ++q) c[mt][nt][q] = 0.f;

        #pragma unroll
        for (int k0 = 0; k0 < 128; k0 += 16) {
            uint32_t a[4][4], bb[2][4];
            #pragma unroll
            for (int mt = 0; mt < 4; ++mt)
                ldm_x4(a[mt], pA + mt * (16 * LDAB) + k0 * 2);
            #pragma unroll
            for (int p = 0; p < 2; ++p)
                ldm_x4(bb[p], pB + p * (16 * LDAB) + k0 * 2);
            #pragma unroll
            for (int mt = 0; mt < 4; ++mt)
                #pragma unroll
                for (int nt = 0; nt < 4; ++nt)
                    mma_bf16(c[mt][nt], a[mt], bb[nt >> 1][nt & 1], bb[nt >> 1][2 + (nt & 1)]);
        }

        // epilogue: bias + (jb==0 ? qscale) + bf16, stage in smem
        float s = (jb == 0) ? QSCALE : 1.0f;
        #pragma unroll
        for (int nt = 0; nt < 4; ++nt) {
            int col = warp_n * 32 + nt * 8 + 2 * tg;
            float b0v = qkv_b[jb * 128 + col];
            float b1v = qkv_b[jb * 128 + col + 1];
            #pragma unroll
            for (int mt = 0; mt < 4; ++mt) {
                int row = warp_m * 64 + mt * 16 + g;
                __nv_bfloat162 lo = __floats2bfloat162_rn((c[mt][nt][0] + b0v) * s,
                                                          (c[mt][nt][1] + b1v) * s);
                __nv_bfloat162 hi = __floats2bfloat162_rn((c[mt][nt][2] + b0v) * s,
                                                          (c[mt][nt][3] + b1v) * s);
                *(__nv_bfloat162*)(sC + row * LDAB + col * 2) = lo;
                *(__nv_bfloat162*)(sC + (row + 8) * LDAB + col * 2) = hi;
            }
        }
        __syncthreads();

        if (jb < 2) {
            const __nv_bfloat16* Bn = g_wqkv + (size_t)(jb + 1) * 128 * 128;
            for (int e = tid; e < 2048; e += 256) {
                int r = e >> 4, j = e & 15;
                *(uint4*)(sB + r * LDAB + j * 16) = *(const uint4*)(Bn + r * 128 + j * 8);
            }
        }
        for (int e = tid; e < 2048; e += 256) {
            int r = e >> 4, j = e & 15;
            *(uint4*)(g_qkv + (row0 + r) * 384 + jb * 128 + j * 8) =
                *(uint4*)(sC + r * LDAB + j * 16);
        }
        __syncthreads();
    }
}

// ---------------- K3: per-window attention core (fp32) ----------------
#define SR  385
#define SSR 56
#define ATTN_SMEM ((64 * SR + 56 * SSR) * 4)   // 111104 B -> 2 CTAs/SM
__global__ __launch_bounds__(256, 2) void attn_kernel(const float* __restrict__ attn_mask) {
    extern __shared__ float smf[];
    float* sX = smf;                 // [64][385] tokens x (Q|K|V)
    float* sS = smf + 64 * SR;       // [56][56] per-head scores

    int wi = blockIdx.x, wimg = wi & (NWIMG - 1), tid = threadIdx.x;

    const __nv_bfloat16* src = g_qkv + (size_t)wi * Nwin * 384;
    for (int e = tid; e < Nwin * 48; e += 256) {
        int n = e / 48, g = e % 48;
        uint4 raw = *(const uint4*)(src + n * 384 + g * 8);
        const __nv_bfloat162* p = (const __nv_bfloat162*)&raw;
        float* d = sX + n * SR + g * 8;
        #pragma unroll
        for (int i = 0; i < 4; ++i) {
            float2 f = __bfloat1622float2(p[i]);
            d[2 * i] = f.x; d[2 * i + 1] = f.y;
        }
    }
    __syncthreads();

    int ty = tid >> 4, tx = tid & 15;
    int ty2 = tid >> 5, tx2 = tid & 31;
    int warp = tid >> 5, lane = tid & 31;

    #pragma unroll 1
    for (int hd = 0; hd < HEADS; ++hd) {
        float acc[4][4];
        #pragma unroll
        for (int r = 0; r < 4; ++r)
            #pragma unroll
            for (int s2 = 0; s2 < 4; ++s2) acc[r][s2] = 0.f;
        const float* Qh = sX + hd * DHEAD;
        const float* Kh = sX + 128 + hd * DHEAD;
        #pragma unroll 8
        for (int c = 0; c < DHEAD; ++c) {
            float qv[4], kv[4];
            #pragma unroll
            for (int r = 0; r < 4; ++r)  qv[r]  = Qh[(ty + r * 16) * SR + c];
            #pragma unroll
            for (int s2 = 0; s2 < 4; ++s2) kv[s2] = Kh[(tx + s2 * 16) * SR + c];
            #pragma unroll
            for (int r = 0; r < 4; ++r)
                #pragma unroll
                for (int s2 = 0; s2 < 4; ++s2) acc[r][s2] += qv[r] * kv[s2];
        }
        const float* Bh = g_bias + hd * (Nwin * Nwin);
        const float* Mh = attn_mask + (size_t)wimg * (Nwin * Nwin);
        #pragma unroll
        for (int r = 0; r < 4; ++r) {
            int n = ty + r * 16;
            if (n < Nwin) {
                #pragma unroll
                for (int s2 = 0; s2 < 4; ++s2) {
                    int m = tx + s2 * 16;
                    if (m < Nwin)
                        sS[n * SSR + m] = acc[r][s2] + Bh[n * Nwin + m] + Mh[n * Nwin + m];
                }
            }
        }
        __syncthreads();

        for (int n = warp; n < Nwin; n += 8) {
            float* row = sS + n * SSR;
            float v0 = row[lane];
            float v1 = (lane + 32 < Nwin) ? row[lane + 32] : -1e30f;
            float mx = fmaxf(v0, v1);
            #pragma unroll
            for (int o = 16; o > 0; o >>= 1)
                mx = fmaxf(mx, __shfl_xor_sync(0xffffffff, mx, o));
            float e0 = __expf(v0 - mx);
            float e1 = (lane + 32 < Nwin) ? __expf(v1 - mx) : 0.f;
            float s = e0 + e1;
            #pragma unroll
            for (int o = 16; o > 0; o >>= 1)
                s += __shfl_xor_sync(0xffffffff, s, o);
            float inv = 1.0f / s;
            row[lane] = e0 * inv;
            if (lane + 32 < Nwin) row[lane + 32] = e1 * inv;
        }
        __syncthreads();

        float po[7];
        #pragma unroll
        for (int k = 0; k < 7; ++k) po[k] = 0.f;
        const float* Vh = sX + 256 + hd * DHEAD + tx2;
        #pragma unroll 7
        for (int m = 0; m < Nwin; ++m) {
            float vv = Vh[m * SR];
            #pragma unroll
            for (int k = 0; k < 7; ++k)
                po[k] += sS[(ty2 + 8 * k) * SSR + m] * vv;
        }
        __nv_bfloat16* dst = g_attn + (size_t)wi * Nwin * 128 + hd * DHEAD + tx2;
        #pragma unroll
        for (int k = 0; k < 7; ++k) {
            int n = ty2 + 8 * k;
            if (n < Nwin) dst[(size_t)n * 128] = __float2bfloat16(po[k]);
        }
        __syncthreads();
    }
}

// ---------------- K4: proj GEMM (mma.sync bf16) ----------------
#define GP_SMEM (2 * TILE_B)
__global__ __launch_bounds__(256, 2) void gemm_proj_kernel(const float* __restrict__ proj_b) {
    extern __shared__ __align__(16) char sm[];
    char* sA = sm;
    char* sB = sm + TILE_B;

    int tid = threadIdx.x, wid = tid >> 5, lane = tid & 31;
    int warp_m = wid >> 2, warp_n = wid & 3;

    const __nv_bfloat16* A = g_attn + (size_t)blockIdx.x * (128 * 128);
    for (int e = tid; e < 2048; e += 256) {
        int r = e >> 4, j = e & 15;
        *(uint4*)(sA + r * LDAB + j * 16) = *(const uint4*)(A + r * 128 + j * 8);
    }
    for (int e = tid; e < 2048; e += 256) {
        int r = e >> 4, j = e & 15;
        *(uint4*)(sB + r * LDAB + j * 16) = *(const uint4*)(g_wproj + r * 128 + j * 8);
    }
    __syncthreads();

    uint32_t pA = smem_u32(sA) + (uint32_t)((warp_m * 64 + (lane & 15)) * LDAB + ((lane >> 4) << 4));
    uint32_t pB = smem_u32(sB) + (uint32_t)((warp_n * 32 + (lane & 15)) * LDAB + ((lane >> 4) << 4));

    float c[4][4][4];
    #pragma unroll
    for (int mt = 0; mt < 4; ++mt)
        #pragma unroll
        for (int nt = 0; nt < 4; ++nt)
            #pragma unroll
            for (int q = 0; q < 4; ++q) c[mt][nt][q] = 0.f;

    #pragma unroll
    for (int k0 = 0; k0 < 128; k0 += 16) {
        uint32_t a[4][4], bb[2][4];
        #pragma unroll
        for (int mt = 0; mt < 4; ++mt)
            ldm_x4(a[mt], pA + mt * (16 * LDAB) + k0 * 2);
        #pragma unroll
        for (int p = 0; p < 2; ++p)
            ldm_x4(bb[p], pB + p * (16 * LDAB) + k0 * 2);
        #pragma unroll
        for (int mt = 0; mt < 4; ++mt)
            #pragma unroll
            for (int nt = 0; nt < 4; ++nt)
                mma_bf16(c[mt][nt], a[mt], bb[nt >> 1][nt & 1], bb[nt >> 1][2 + (nt & 1)]);
    }
    __syncthreads();   // before overwriting sA/sB with the fp32 stage

    float* sC = (float*)sm;          // [128][132] fp32 (67584 B <= 69632)
    int g = lane >> 2, tg = lane & 3;
    #pragma unroll
    for (int nt = 0; nt < 4; ++nt) {
        int col = warp_n * 32 + nt * 8 + 2 * tg;
        #pragma unroll
        for (int mt = 0; mt < 4; ++mt) {
            int row = warp_m * 64 + mt * 16 + g;
            *(float2*)(sC + row * 132 + col)       = make_float2(c[mt][nt][0], c[mt][nt][1]);
            *(float2*)(sC + (row + 8) * 132 + col) = make_float2(c[mt][nt][2], c[mt][nt][3]);
        }
    }
    __syncthreads();

    size_t row0 = (size_t)blockIdx.x * 128;
    for (int e = tid; e < 4096; e += 256) {
        int r = e >> 5, q = e & 31;
        float4 a = *(const float4*)(sC + r * 132 + q * 4);
        float4 b = *(const float4*)(proj_b + q * 4);
        float4 o;
        o.x = a.x + b.x; o.y = a.y + b.y; o.z = a.z + b.z; o.w = a.w + b.w;
        *(float4*)(g_owin + (row0 + r) * 128 + q * 4) = o;
    }
}

// ---------------- K5: window reverse + unshift + residual ----------------
__global__ void reverse_kernel(const float* __restrict__ x,
                               float* __restrict__ out) {
    __shared__ float s[128 * 57];
    int h = blockIdx.x, half = blockIdx.y, b = blockIdx.z;
    int w0 = half * 56;
    int tid = threadIdx.x;

    int h2 = h - SHIFT; if (h2 < 0) h2 += Hdim;
    int whh = h2 / Mwin, rr = h2 % Mwin;

    for (int e = tid; e < 56 * 128; e += 256) {
        int wl = e >> 7, c = e & 127;
        int w = w0 + wl;
        int w2 = w - SHIFT; if (w2 < 0) w2 += Wdim;
        int wi = b * NWIMG + whh * NHw + (w2 / Mwin);
        int n  = rr * Mwin + (w2 % Mwin);
        s[c * 57 + wl] = g_owin[((size_t)wi * Nwin + n) * 128 + c];
    }
    __syncthreads();

    size_t base = (size_t)b * Cdim * (Hdim * Wdim) + (size_t)h * Wdim + w0;
    for (int e = tid; e < 128 * 56; e += 256) {
        int c = e / 56, wl = e % 56;
        size_t gi = base + (size_t)c * (Hdim * Wdim) + wl;
        out[gi] = x[gi] + s[c * 57 + wl];
    }
}

// ---------------- launch ----------------
extern "C" void kernel_launch(void* const* d_in, const int* in_sizes, int n_in,
                              void* d_out, int out_size) {
    const float* x          = (const float*)d_in[0];
    const float* norm_w     = (const float*)d_in[1];
    const float* norm_b     = (const float*)d_in[2];
    const float* qkv_w      = (const float*)d_in[3];
    const float* qkv_b      = (const float*)d_in[4];
    const float* proj_w     = (const float*)d_in[5];
    const float* proj_b     = (const float*)d_in[6];
    const float* bias_table = (const float*)d_in[7];
    const int*   rel_index  = (const int*)  d_in[8];
    const float* attn_mask  = (const float*)d_in[9];
    float* out = (float*)d_out;

    cudaFuncSetAttribute(gemm_qkv_kernel,  cudaFuncAttributeMaxDynamicSharedMemorySize, GQ_SMEM);
    cudaFuncSetAttribute(gemm_proj_kernel, cudaFuncAttributeMaxDynamicSharedMemorySize, GP_SMEM);
    cudaFuncSetAttribute(attn_kernel,      cudaFuncAttributeMaxDynamicSharedMemorySize, ATTN_SMEM);

    int prep_total = 384 * 128 + 128 * 128 + HEADS * Nwin * Nwin;
    prep_kernel<<<(prep_total + 255) / 256, 256>>>(qkv_w, proj_w, bias_table, rel_index);
    ln_window_kernel<<<dim3(Hdim, 2, Bsz), 256>>>(x, norm_w, norm_b);
    gemm_qkv_kernel<<<NTOK / 128, 256, GQ_SMEM>>>(qkv_b);
    attn_kernel<<<NWTOT, 256, ATTN_SMEM>>>(attn_mask);
    gemm_proj_kernel<<<NTOK / 128, 256, GP_SMEM>>>(proj_b);
    reverse_kernel<<<dim3(Hdim, 2, Bsz), 256>>>(x, out);
}

// round 4
// speedup vs baseline: 6.7774x; 1.7735x over previous
#include <cuda_runtime.h>
#include <cuda_bf16.h>
#include <cstdint>

#define Bsz   32
#define Cdim  128
#define Hdim  112
#define Wdim  112
#define Mwin  7
#define Nwin  49
#define NHw   16
#define NWIMG 256
#define NWTOT 8192
#define HEADS 4
#define DHEAD 32
#define SHIFT 3
#define NTOK  (NWTOT * Nwin)          // 401408
#define QSCALE 0.17677669529663687f   // 1/sqrt(32)

// ---------------- scratch (device globals; no allocation) ----------------
__device__ __nv_bfloat16 g_win [(size_t)NTOK * 128];   // LN+shifted tokens (bf16)
__device__ __nv_bfloat16 g_qkv [(size_t)NTOK * 384];   // QKV (bf16, Q pre-scaled)
__device__ __nv_bfloat16 g_attn[(size_t)NTOK * 128];   // attention output (bf16)
__device__ float         g_owin[(size_t)NTOK * 128];   // proj output (fp32)
__device__ __nv_bfloat16 g_wqkv [384 * 128];           // bf16 weights [j][k]
__device__ __nv_bfloat16 g_wproj[128 * 128];
__device__ float         g_bias [HEADS * Nwin * Nwin];
__device__ __nv_bfloat16 g_cmb  [(size_t)NWIMG * HEADS * 64 * 56];  // bias+mask combined

// ---------------- helpers ----------------
__device__ __forceinline__ uint32_t smem_u32(const void* p) {
    uint32_t a;
    asm("{ .reg .u64 t; cvta.to.shared.u64 t, %1; cvt.u32.u64 %0, t; }" : "=r"(a) : "l"(p));
    return a;
}
__device__ __forceinline__ void ldm_x4(uint32_t r[4], uint32_t addr) {
    asm volatile("ldmatrix.sync.aligned.m8n8.x4.shared.b16 {%0,%1,%2,%3}, [%4];"
        : "=r"(r[0]), "=r"(r[1]), "=r"(r[2]), "=r"(r[3]) : "r"(addr));
}
__device__ __forceinline__ void mma_bf16(float c[4], const uint32_t a[4],
                                         uint32_t b0, uint32_t b1) {
    asm volatile("mma.sync.aligned.m16n8k16.row.col.f32.bf16.bf16.f32 "
        "{%0,%1,%2,%3}, {%4,%5,%6,%7}, {%8,%9}, {%0,%1,%2,%3};"
        : "+f"(c[0]), "+f"(c[1]), "+f"(c[2]), "+f"(c[3])
        : "r"(a[0]), "r"(a[1]), "r"(a[2]), "r"(a[3]), "r"(b0), "r"(b1));
}
__device__ __forceinline__ uint32_t pack_bf16x2(float a, float b) {
    __nv_bfloat162 t = __floats2bfloat162_rn(a, b);
    return *(uint32_t*)&t;
}

#define LDAB 272          // GEMM smem row stride in bytes (136 bf16)
#define TILE_B 34816      // 128 * 272

// ---------------- K0: weight bf16 conversion + bias gather ----------------
__global__ void prep_kernel(const float* __restrict__ qkv_w,
                            const float* __restrict__ proj_w,
                            const float* __restrict__ bias_table,
                            const int*   __restrict__ rel_index) {
    int i = blockIdx.x * blockDim.x + threadIdx.x;
    if (i < 384 * 128) {
        g_wqkv[i] = __float2bfloat16_rn(qkv_w[i]);
    } else if (i < 384 * 128 + 128 * 128) {
        int t = i - 384 * 128;
        g_wproj[t] = __float2bfloat16_rn(proj_w[t]);
    } else if (i < 384 * 128 + 128 * 128 + HEADS * Nwin * Nwin) {
        int t = i - (384 * 128 + 128 * 128);
        int hd = t / (Nwin * Nwin), nm = t % (Nwin * Nwin);
        g_bias[t] = bias_table[rel_index[nm] * HEADS + hd];
    }
}

// ---------------- K0b: combined bias+mask (bf16), padded to [64][56] ----------------
__global__ void cmb_kernel(const float* __restrict__ attn_mask) {
    int i = blockIdx.x * blockDim.x + threadIdx.x;
    if (i >= NWIMG * HEADS * 64 * 56) return;
    int m = i % 56; int t = i / 56;
    int n = t & 63; t >>= 6;
    int hd = t & 3; int wimg = t >> 2;
    float v;
    if (n >= Nwin)      v = 0.f;
    else if (m >= Nwin) v = -30000.f;
    else v = g_bias[hd * (Nwin * Nwin) + n * Nwin + m]
           + attn_mask[((size_t)wimg * Nwin + n) * Nwin + m];
    g_cmb[i] = __float2bfloat16_rn(v);
}

// ---------------- K1: LayerNorm + shift + window partition (bf16 out) ----------------
#define RS 132
__global__ void ln_window_kernel(const float* __restrict__ x,
                                 const float* __restrict__ nw,
                                 const float* __restrict__ nb) {
    __shared__ float s[56 * RS];
    int h = blockIdx.x, half = blockIdx.y, b = blockIdx.z;
    int w0 = half * 56;
    int tid = threadIdx.x;

    const float* xp = x + (size_t)b * Cdim * (Hdim * Wdim) + (size_t)h * Wdim + w0;
    for (int e = tid; e < 56 * 128; e += 256) {
        int c = e / 56, w = e % 56;
        s[w * RS + c] = xp[(size_t)c * (Hdim * Wdim) + w];
    }
    __syncthreads();

    int warp = tid >> 5, lane = tid & 31;
    for (int wl = warp; wl < 56; wl += 8) {
        float4 v = *(const float4*)&s[wl * RS + lane * 4];
        float sum = v.x + v.y + v.z + v.w;
        float sq  = v.x * v.x + v.y * v.y + v.z * v.z + v.w * v.w;
        #pragma unroll
        for (int o = 16; o > 0; o >>= 1) {
            sum += __shfl_xor_sync(0xffffffff, sum, o);
            sq  += __shfl_xor_sync(0xffffffff, sq,  o);
        }
        float mu  = sum * (1.0f / 128.0f);
        float var = sq * (1.0f / 128.0f) - mu * mu;
        float inv = rsqrtf(var + 1e-5f);

        int c0 = lane * 4;
        float4 g  = *(const float4*)&nw[c0];
        float4 be = *(const float4*)&nb[c0];
        __align__(8) __nv_bfloat162 o2[2];
        o2[0] = __floats2bfloat162_rn((v.x - mu) * inv * g.x + be.x,
                                      (v.y - mu) * inv * g.y + be.y);
        o2[1] = __floats2bfloat162_rn((v.z - mu) * inv * g.z + be.z,
                                      (v.w - mu) * inv * g.w + be.w);

        int ws = w0 + wl;
        int hd = h - SHIFT;  if (hd < 0) hd += Hdim;
        int wd = ws - SHIFT; if (wd < 0) wd += Wdim;
        int wi = b * NWIMG + (hd / Mwin) * NHw + (wd / Mwin);
        int n  = (hd % Mwin) * Mwin + (wd % Mwin);
        *(uint2*)&g_win[((size_t)wi * Nwin + n) * 128 + c0] = *(uint2*)o2;
    }
}

// ---------------- K2: QKV GEMM (mma.sync bf16) ----------------
#define GQ_SMEM (3 * TILE_B)
__global__ __launch_bounds__(256, 2) void gemm_qkv_kernel(const float* __restrict__ qkv_b) {
    extern __shared__ __align__(16) char sm[];
    char* sA = sm;
    char* sB = sm + TILE_B;
    char* sC = sm + 2 * TILE_B;

    int tid = threadIdx.x, wid = tid >> 5, lane = tid & 31;
    int warp_m = wid >> 2, warp_n = wid & 3;

    const __nv_bfloat16* A = g_win + (size_t)blockIdx.x * (128 * 128);
    for (int e = tid; e < 2048; e += 256) {
        int r = e >> 4, j = e & 15;
        *(uint4*)(sA + r * LDAB + j * 16) = *(const uint4*)(A + r * 128 + j * 8);
    }
    for (int e = tid; e < 2048; e += 256) {
        int r = e >> 4, j = e & 15;
        *(uint4*)(sB + r * LDAB + j * 16) = *(const uint4*)(g_wqkv + r * 128 + j * 8);
    }
    __syncthreads();

    uint32_t pA = smem_u32(sA) + (uint32_t)((warp_m * 64 + (lane & 15)) * LDAB + ((lane >> 4) << 4));
    uint32_t pB = smem_u32(sB) + (uint32_t)((warp_n * 32 + (lane & 15)) * LDAB + ((lane >> 4) << 4));
    size_t row0 = (size_t)blockIdx.x * 128;
    int g = lane >> 2, tg = lane & 3;

    #pragma unroll 1
    for (int jb = 0; jb < 3; ++jb) {
        float c[4][4][4];
        #pragma unroll
        for (int mt = 0; mt < 4; ++mt)
            #pragma unroll
            for (int nt = 0; nt < 4; ++nt)
                #pragma unroll
                for (int q = 0; q < 4; ++q) c[mt][nt][q] = 0.f;

        #pragma unroll
        for (int k0 = 0; k0 < 128; k0 += 16) {
            uint32_t a[4][4], bb[2][4];
            #pragma unroll
            for (int mt = 0; mt < 4; ++mt)
                ldm_x4(a[mt], pA + mt * (16 * LDAB) + k0 * 2);
            #pragma unroll
            for (int p = 0; p < 2; ++p)
                ldm_x4(bb[p], pB + p * (16 * LDAB) + k0 * 2);
            #pragma unroll
            for (int mt = 0; mt < 4; ++mt)
                #pragma unroll
                for (int nt = 0; nt < 4; ++nt)
                    mma_bf16(c[mt][nt], a[mt], bb[nt >> 1][nt & 1], bb[nt >> 1][2 + (nt & 1)]);
        }

        float s = (jb == 0) ? QSCALE : 1.0f;
        #pragma unroll
        for (int nt = 0; nt < 4; ++nt) {
            int col = warp_n * 32 + nt * 8 + 2 * tg;
            float b0v = qkv_b[jb * 128 + col];
            float b1v = qkv_b[jb * 128 + col + 1];
            #pragma unroll
            for (int mt = 0; mt < 4; ++mt) {
                int row = warp_m * 64 + mt * 16 + g;
                __nv_bfloat162 lo = __floats2bfloat162_rn((c[mt][nt][0] + b0v) * s,
                                                          (c[mt][nt][1] + b1v) * s);
                __nv_bfloat162 hi = __floats2bfloat162_rn((c[mt][nt][2] + b0v) * s,
                                                          (c[mt][nt][3] + b1v) * s);
                *(__nv_bfloat162*)(sC + row * LDAB + col * 2) = lo;
                *(__nv_bfloat162*)(sC + (row + 8) * LDAB + col * 2) = hi;
            }
        }
        __syncthreads();

        if (jb < 2) {
            const __nv_bfloat16* Bn = g_wqkv + (size_t)(jb + 1) * 128 * 128;
            for (int e = tid; e < 2048; e += 256) {
                int r = e >> 4, j = e & 15;
                *(uint4*)(sB + r * LDAB + j * 16) = *(const uint4*)(Bn + r * 128 + j * 8);
            }
        }
        for (int e = tid; e < 2048; e += 256) {
            int r = e >> 4, j = e & 15;
            *(uint4*)(g_qkv + (row0 + r) * 384 + jb * 128 + j * 8) =
                *(uint4*)(sC + r * LDAB + j * 16);
        }
        __syncthreads();
    }
}

// ---------------- K3: per-window attention core (mma.sync, FA2-style) ----------------
// CTA = 1 window, 128 threads, warp = head.
// smem: sQK [64][264] bf16 (row stride 528B), sVT [128 d][72 tok] bf16 (stride 144B)
#define AQK 264
#define AVT 72
#define ATTN_SMEM (64 * AQK * 2 + 128 * AVT * 2)   // 52224 B
__global__ __launch_bounds__(128, 4) void attn_kernel() {
    extern __shared__ __align__(16) __nv_bfloat16 smb[];
    __nv_bfloat16* sQK = smb;
    __nv_bfloat16* sVT = smb + 64 * AQK;

    int wi = blockIdx.x, wimg = wi & (NWIMG - 1), tid = threadIdx.x;
    int wid = tid >> 5, lane = tid & 31;

    const __nv_bfloat16* src = g_qkv + (size_t)wi * Nwin * 384;
    // Q|K rows (cols 0..255), uint4-vectorized
    for (int e = tid; e < Nwin * 32; e += 128) {
        int n = e >> 5, j = e & 31;
        *(uint4*)&sQK[n * AQK + j * 8] = *(const uint4*)(src + n * 384 + j * 8);
    }
    // V transposed: sVT[d][n]
    for (int e = tid; e < Nwin * 16; e += 128) {
        int n = e >> 4, j = e & 15;
        uint4 raw = *(const uint4*)(src + n * 384 + 256 + j * 8);
        __nv_bfloat16 tmp[8]; *(uint4*)tmp = raw;
        #pragma unroll
        for (int q = 0; q < 8; ++q) sVT[(j * 8 + q) * AVT + n] = tmp[q];
    }
    // zero pads: sQK rows 49..63
    for (int e = tid; e < 15 * 33; e += 128) {
        int r = 49 + e / 33, j = e % 33;
        *(uint4*)&sQK[r * AQK + j * 8] = make_uint4(0, 0, 0, 0);
    }
    // zero pads: sVT cols 49..71 for all 128 d-rows
    for (int e = tid; e < 128 * 23; e += 128) {
        int d = e / 23, c = 49 + e % 23;
        sVT[d * AVT + c] = __float2bfloat16(0.f);
    }
    __syncthreads();

    int hd = wid;
    int g = lane >> 2, tg = lane & 3;
    uint32_t sqk = smem_u32(sQK), svt = smem_u32(sVT);
    int lrow = lane & 15, lsel = (lane >> 4) << 4;

    // held K fragments: kb[ntp][kt][4]
    uint32_t kb[4][2][4];
    #pragma unroll
    for (int ntp = 0; ntp < 4; ++ntp)
        #pragma unroll
        for (int kt = 0; kt < 2; ++kt)
            ldm_x4(kb[ntp][kt],
                   sqk + (uint32_t)((ntp * 16 + lrow) * (AQK * 2) + (128 + hd * 32 + kt * 16) * 2 + lsel));

    const __nv_bfloat162* cm =
        (const __nv_bfloat162*)(g_cmb + (size_t)(wimg * HEADS + hd) * 64 * 56);
    __nv_bfloat16* dst = g_attn + (size_t)wi * Nwin * 128 + hd * 32;

    #pragma unroll 1
    for (int mt = 0; mt < 4; ++mt) {
        // Q fragments
        uint32_t qf[2][4];
        #pragma unroll
        for (int kt = 0; kt < 2; ++kt)
            ldm_x4(qf[kt],
                   sqk + (uint32_t)((mt * 16 + lrow) * (AQK * 2) + (hd * 32 + kt * 16) * 2 + lsel));

        int rA = mt * 16 + g, rB = rA + 8;
        // init S accumulators with bias+mask
        float s[7][4];
        #pragma unroll
        for (int nt = 0; nt < 7; ++nt) {
            float2 fa = __bfloat1622float2(cm[(rA * 56 + nt * 8 + 2 * tg) >> 1]);
            float2 fb = __bfloat1622float2(cm[(rB * 56 + nt * 8 + 2 * tg) >> 1]);
            s[nt][0] = fa.x; s[nt][1] = fa.y; s[nt][2] = fb.x; s[nt][3] = fb.y;
        }
        // S = Q K^T (+init)
        #pragma unroll
        for (int kt = 0; kt < 2; ++kt)
            #pragma unroll
            for (int nt = 0; nt < 7; ++nt)
                mma_bf16(s[nt], qf[kt], kb[nt >> 1][kt][nt & 1], kb[nt >> 1][kt][2 + (nt & 1)]);

        // softmax (rows rA: s[nt][0..1], rB: s[nt][2..3]); quad = lanes sharing g
        float mxA = -1e30f, mxB = -1e30f;
        #pragma unroll
        for (int nt = 0; nt < 7; ++nt) {
            mxA = fmaxf(mxA, fmaxf(s[nt][0], s[nt][1]));
            mxB = fmaxf(mxB, fmaxf(s[nt][2], s[nt][3]));
        }
        mxA = fmaxf(mxA, __shfl_xor_sync(0xffffffff, mxA, 1));
        mxA = fmaxf(mxA, __shfl_xor_sync(0xffffffff, mxA, 2));
        mxB = fmaxf(mxB, __shfl_xor_sync(0xffffffff, mxB, 1));
        mxB = fmaxf(mxB, __shfl_xor_sync(0xffffffff, mxB, 2));
        float sumA = 0.f, sumB = 0.f;
        #pragma unroll
        for (int nt = 0; nt < 7; ++nt) {
            s[nt][0] = __expf(s[nt][0] - mxA); sumA += s[nt][0];
            s[nt][1] = __expf(s[nt][1] - mxA); sumA += s[nt][1];
            s[nt][2] = __expf(s[nt][2] - mxB); sumB += s[nt][2];
            s[nt][3] = __expf(s[nt][3] - mxB); sumB += s[nt][3];
        }
        sumA += __shfl_xor_sync(0xffffffff, sumA, 1);
        sumA += __shfl_xor_sync(0xffffffff, sumA, 2);
        sumB += __shfl_xor_sync(0xffffffff, sumB, 1);
        sumB += __shfl_xor_sync(0xffffffff, sumB, 2);
        float invA = 1.0f / sumA, invB = 1.0f / sumB;
        #pragma unroll
        for (int nt = 0; nt < 7; ++nt) {
            s[nt][0] *= invA; s[nt][1] *= invA;
            s[nt][2] *= invB; s[nt][3] *= invB;
        }

        // pack P into A-fragments (k-tiles over token dim; nt=7 is zero pad)
        uint32_t pf[4][4];
        #pragma unroll
        for (int kt = 0; kt < 4; ++kt) {
            int nt0 = 2 * kt, nt1 = 2 * kt + 1;
            pf[kt][0] = pack_bf16x2(s[nt0][0], s[nt0][1]);
            pf[kt][1] = pack_bf16x2(s[nt0][2], s[nt0][3]);
            if (nt1 < 7) {
                pf[kt][2] = pack_bf16x2(s[nt1][0], s[nt1][1]);
                pf[kt][3] = pack_bf16x2(s[nt1][2], s[nt1][3]);
            } else {
                pf[kt][2] = 0u; pf[kt][3] = 0u;
            }
        }

        // O = P V
        float o[4][4];
        #pragma unroll
        for (int dt = 0; dt < 4; ++dt)
            #pragma unroll
            for (int q = 0; q < 4; ++q) o[dt][q] = 0.f;
        #pragma unroll
        for (int kt = 0; kt < 4; ++kt) {
            uint32_t vb[2][4];
            #pragma unroll
            for (int dp = 0; dp < 2; ++dp)
                ldm_x4(vb[dp],
                       svt + (uint32_t)((hd * 32 + dp * 16 + lrow) * (AVT * 2) + kt * 32 + lsel));
            #pragma unroll
            for (int dt = 0; dt < 4; ++dt)
                mma_bf16(o[dt], pf[kt], vb[dt >> 1][dt & 1], vb[dt >> 1][2 + (dt & 1)]);
        }

        // store O rows
        int nA = mt * 16 + g, nB = nA + 8;
        #pragma unroll
        for (int dt = 0; dt < 4; ++dt) {
            int col = dt * 8 + 2 * tg;
            if (nA < Nwin) {
                __nv_bfloat162 v = __floats2bfloat162_rn(o[dt][0], o[dt][1]);
                *(__nv_bfloat162*)&dst[(size_t)nA * 128 + col] = v;
            }
            if (nB < Nwin) {
                __nv_bfloat162 v = __floats2bfloat162_rn(o[dt][2], o[dt][3]);
                *(__nv_bfloat162*)&dst[(size_t)nB * 128 + col] = v;
            }
        }
    }
}

// ---------------- K4: proj GEMM (mma.sync bf16) ----------------
#define GP_SMEM (2 * TILE_B)
__global__ __launch_bounds__(256, 2) void gemm_proj_kernel(const float* __restrict__ proj_b) {
    extern __shared__ __align__(16) char sm[];
    char* sA = sm;
    char* sB = sm + TILE_B;

    int tid = threadIdx.x, wid = tid >> 5, lane = tid & 31;
    int warp_m = wid >> 2, warp_n = wid & 3;

    const __nv_bfloat16* A = g_attn + (size_t)blockIdx.x * (128 * 128);
    for (int e = tid; e < 2048; e += 256) {
        int r = e >> 4, j = e & 15;
        *(uint4*)(sA + r * LDAB + j * 16) = *(const uint4*)(A + r * 128 + j * 8);
    }
    for (int e = tid; e < 2048; e += 256) {
        int r = e >> 4, j = e & 15;
        *(uint4*)(sB + r * LDAB + j * 16) = *(const uint4*)(g_wproj + r * 128 + j * 8);
    }
    __syncthreads();

    uint32_t pA = smem_u32(sA) + (uint32_t)((warp_m * 64 + (lane & 15)) * LDAB + ((lane >> 4) << 4));
    uint32_t pB = smem_u32(sB) + (uint32_t)((warp_n * 32 + (lane & 15)) * LDAB + ((lane >> 4) << 4));

    float c[4][4][4];
    #pragma unroll
    for (int mt = 0; mt < 4; ++mt)
        #pragma unroll
        for (int nt = 0; nt < 4; ++nt)
            #pragma unroll
            for (int q = 0; q < 4; ++q) c[mt][nt][q] = 0.f;

    #pragma unroll
    for (int k0 = 0; k0 < 128; k0 += 16) {
        uint32_t a[4][4], bb[2][4];
        #pragma unroll
        for (int mt = 0; mt < 4; ++mt)
            ldm_x4(a[mt], pA + mt * (16 * LDAB) + k0 * 2);
        #pragma unroll
        for (int p = 0; p < 2; ++p)
            ldm_x4(bb[p], pB + p * (16 * LDAB) + k0 * 2);
        #pragma unroll
        for (int mt = 0; mt < 4; ++mt)
            #pragma unroll
            for (int nt = 0; nt < 4; ++nt)
                mma_bf16(c[mt][nt], a[mt], bb[nt >> 1][nt & 1], bb[nt >> 1][2 + (nt & 1)]);
    }
    __syncthreads();

    float* sC = (float*)sm;          // [128][132] fp32
    int g = lane >> 2, tg = lane & 3;
    #pragma unroll
    for (int nt = 0; nt < 4; ++nt) {
        int col = warp_n * 32 + nt * 8 + 2 * tg;
        #pragma unroll
        for (int mt = 0; mt < 4; ++mt) {
            int row = warp_m * 64 + mt * 16 + g;
            *(float2*)(sC + row * 132 + col)       = make_float2(c[mt][nt][0], c[mt][nt][1]);
            *(float2*)(sC + (row + 8) * 132 + col) = make_float2(c[mt][nt][2], c[mt][nt][3]);
        }
    }
    __syncthreads();

    size_t row0 = (size_t)blockIdx.x * 128;
    for (int e = tid; e < 4096; e += 256) {
        int r = e >> 5, q = e & 31;
        float4 a = *(const float4*)(sC + r * 132 + q * 4);
        float4 b = *(const float4*)(proj_b + q * 4);
        float4 o;
        o.x = a.x + b.x; o.y = a.y + b.y; o.z = a.z + b.z; o.w = a.w + b.w;
        *(float4*)(g_owin + (row0 + r) * 128 + q * 4) = o;
    }
}

// ---------------- K5: window reverse + unshift + residual ----------------
__global__ void reverse_kernel(const float* __restrict__ x,
                               float* __restrict__ out) {
    __shared__ float s[128 * 57];
    int h = blockIdx.x, half = blockIdx.y, b = blockIdx.z;
    int w0 = half * 56;
    int tid = threadIdx.x;

    int h2 = h - SHIFT; if (h2 < 0) h2 += Hdim;
    int whh = h2 / Mwin, rr = h2 % Mwin;

    for (int e = tid; e < 56 * 128; e += 256) {
        int wl = e >> 7, c = e & 127;
        int w = w0 + wl;
        int w2 = w - SHIFT; if (w2 < 0) w2 += Wdim;
        int wi = b * NWIMG + whh * NHw + (w2 / Mwin);
        int n  = rr * Mwin + (w2 % Mwin);
        s[c * 57 + wl] = g_owin[((size_t)wi * Nwin + n) * 128 + c];
    }
    __syncthreads();

    size_t base = (size_t)b * Cdim * (Hdim * Wdim) + (size_t)h * Wdim + w0;
    for (int e = tid; e < 128 * 56; e += 256) {
        int c = e / 56, wl = e % 56;
        size_t gi = base + (size_t)c * (Hdim * Wdim) + wl;
        out[gi] = x[gi] + s[c * 57 + wl];
    }
}

// ---------------- launch ----------------
extern "C" void kernel_launch(void* const* d_in, const int* in_sizes, int n_in,
                              void* d_out, int out_size) {
    const float* x          = (const float*)d_in[0];
    const float* norm_w     = (const float*)d_in[1];
    const float* norm_b     = (const float*)d_in[2];
    const float* qkv_w      = (const float*)d_in[3];
    const float* qkv_b      = (const float*)d_in[4];
    const float* proj_w     = (const float*)d_in[5];
    const float* proj_b     = (const float*)d_in[6];
    const float* bias_table = (const float*)d_in[7];
    const int*   rel_index  = (const int*)  d_in[8];
    const float* attn_mask  = (const float*)d_in[9];
    float* out = (float*)d_out;

    cudaFuncSetAttribute(gemm_qkv_kernel,  cudaFuncAttributeMaxDynamicSharedMemorySize, GQ_SMEM);
    cudaFuncSetAttribute(gemm_proj_kernel, cudaFuncAttributeMaxDynamicSharedMemorySize, GP_SMEM);
    cudaFuncSetAttribute(attn_kernel,      cudaFuncAttributeMaxDynamicSharedMemorySize, ATTN_SMEM);

    int prep_total = 384 * 128 + 128 * 128 + HEADS * Nwin * Nwin;
    prep_kernel<<<(prep_total + 255) / 256, 256>>>(qkv_w, proj_w, bias_table, rel_index);
    int cmb_total = NWIMG * HEADS * 64 * 56;
    cmb_kernel<<<(cmb_total + 255) / 256, 256>>>(attn_mask);
    ln_window_kernel<<<dim3(Hdim, 2, Bsz), 256>>>(x, norm_w, norm_b);
    gemm_qkv_kernel<<<NTOK / 128, 256, GQ_SMEM>>>(qkv_b);
    attn_kernel<<<NWTOT, 128, ATTN_SMEM>>>();
    gemm_proj_kernel<<<NTOK / 128, 256, GP_SMEM>>>(proj_b);
    reverse_kernel<<<dim3(Hdim, 2, Bsz), 256>>>(x, out);
}

// round 5
// speedup vs baseline: 7.1532x; 1.0555x over previous
#include <cuda_runtime.h>
#include <cuda_bf16.h>
#include <cstdint>

#define Bsz   32
#define Cdim  128
#define Hdim  112
#define Wdim  112
#define Mwin  7
#define Nwin  49
#define NHw   16
#define NWIMG 256
#define NWTOT 8192
#define HEADS 4
#define DHEAD 32
#define SHIFT 3
#define NTOK  (NWTOT * Nwin)          // 401408
#define QSCALE 0.17677669529663687f   // 1/sqrt(32)

// ---------------- scratch (device globals; no allocation) ----------------
__device__ __nv_bfloat16 g_win [(size_t)NTOK * 128];   // LN+shifted tokens (bf16)
__device__ __nv_bfloat16 g_qkv [(size_t)NTOK * 384];   // QKV (bf16, Q pre-scaled)
__device__ __nv_bfloat16 g_attn[(size_t)NTOK * 128];   // attention output (bf16)
__device__ __nv_bfloat16 g_owin[(size_t)NTOK * 128];   // proj output (bf16, bias added)
__device__ __nv_bfloat16 g_wqkv [384 * 128];           // bf16 weights [j][k]
__device__ __nv_bfloat16 g_wproj[128 * 128];
__device__ float         g_bias [HEADS * Nwin * Nwin];
__device__ __nv_bfloat16 g_cmb  [(size_t)NWIMG * HEADS * 64 * 56];  // bias+mask combined

// ---------------- helpers ----------------
__device__ __forceinline__ uint32_t smem_u32(const void* p) {
    uint32_t a;
    asm("{ .reg .u64 t; cvta.to.shared.u64 t, %1; cvt.u32.u64 %0, t; }" : "=r"(a) : "l"(p));
    return a;
}
__device__ __forceinline__ void ldm_x4(uint32_t r[4], uint32_t addr) {
    asm volatile("ldmatrix.sync.aligned.m8n8.x4.shared.b16 {%0,%1,%2,%3}, [%4];"
        : "=r"(r[0]), "=r"(r[1]), "=r"(r[2]), "=r"(r[3]) : "r"(addr));
}
__device__ __forceinline__ void mma_bf16(float c[4], const uint32_t a[4],
                                         uint32_t b0, uint32_t b1) {
    asm volatile("mma.sync.aligned.m16n8k16.row.col.f32.bf16.bf16.f32 "
        "{%0,%1,%2,%3}, {%4,%5,%6,%7}, {%8,%9}, {%0,%1,%2,%3};"
        : "+f"(c[0]), "+f"(c[1]), "+f"(c[2]), "+f"(c[3])
        : "r"(a[0]), "r"(a[1]), "r"(a[2]), "r"(a[3]), "r"(b0), "r"(b1));
}
__device__ __forceinline__ uint32_t pack_bf16x2(float a, float b) {
    __nv_bfloat162 t = __floats2bfloat162_rn(a, b);
    return *(uint32_t*)&t;
}

#define LDAB 272          // GEMM smem row stride in bytes (136 bf16)
#define TILE_B 34816      // 128 * 272

// ---------------- K0: weight bf16 conversion + bias gather ----------------
__global__ void prep_kernel(const float* __restrict__ qkv_w,
                            const float* __restrict__ proj_w,
                            const float* __restrict__ bias_table,
                            const int*   __restrict__ rel_index) {
    int i = blockIdx.x * blockDim.x + threadIdx.x;
    if (i < 384 * 128) {
        g_wqkv[i] = __float2bfloat16_rn(qkv_w[i]);
    } else if (i < 384 * 128 + 128 * 128) {
        int t = i - 384 * 128;
        g_wproj[t] = __float2bfloat16_rn(proj_w[t]);
    } else if (i < 384 * 128 + 128 * 128 + HEADS * Nwin * Nwin) {
        int t = i - (384 * 128 + 128 * 128);
        int hd = t / (Nwin * Nwin), nm = t % (Nwin * Nwin);
        g_bias[t] = bias_table[rel_index[nm] * HEADS + hd];
    }
}

// ---------------- K0b: combined bias+mask (bf16), padded to [64][56] ----------------
__global__ void cmb_kernel(const float* __restrict__ attn_mask) {
    int i = blockIdx.x * blockDim.x + threadIdx.x;
    if (i >= NWIMG * HEADS * 64 * 56) return;
    int m = i % 56; int t = i / 56;
    int n = t & 63; t >>= 6;
    int hd = t & 3; int wimg = t >> 2;
    float v;
    if (n >= Nwin)      v = 0.f;
    else if (m >= Nwin) v = -30000.f;
    else v = g_bias[hd * (Nwin * Nwin) + n * Nwin + m]
           + attn_mask[((size_t)wimg * Nwin + n) * Nwin + m];
    g_cmb[i] = __float2bfloat16_rn(v);
}

// ---------------- K1: LayerNorm + shift + window partition (bf16 out) ----------------
#define RS 132
__global__ void ln_window_kernel(const float* __restrict__ x,
                                 const float* __restrict__ nw,
                                 const float* __restrict__ nb) {
    __shared__ float s[56 * RS];
    int h = blockIdx.x, half = blockIdx.y, b = blockIdx.z;
    int w0 = half * 56;
    int tid = threadIdx.x;

    const float* xp = x + (size_t)b * Cdim * (Hdim * Wdim) + (size_t)h * Wdim + w0;
    for (int e = tid; e < 56 * 128; e += 256) {
        int c = e / 56, w = e % 56;
        s[w * RS + c] = xp[(size_t)c * (Hdim * Wdim) + w];
    }
    __syncthreads();

    int warp = tid >> 5, lane = tid & 31;
    for (int wl = warp; wl < 56; wl += 8) {
        float4 v = *(const float4*)&s[wl * RS + lane * 4];
        float sum = v.x + v.y + v.z + v.w;
        float sq  = v.x * v.x + v.y * v.y + v.z * v.z + v.w * v.w;
        #pragma unroll
        for (int o = 16; o > 0; o >>= 1) {
            sum += __shfl_xor_sync(0xffffffff, sum, o);
            sq  += __shfl_xor_sync(0xffffffff, sq,  o);
        }
        float mu  = sum * (1.0f / 128.0f);
        float var = sq * (1.0f / 128.0f) - mu * mu;
        float inv = rsqrtf(var + 1e-5f);

        int c0 = lane * 4;
        float4 g  = *(const float4*)&nw[c0];
        float4 be = *(const float4*)&nb[c0];
        __align__(8) __nv_bfloat162 o2[2];
        o2[0] = __floats2bfloat162_rn((v.x - mu) * inv * g.x + be.x,
                                      (v.y - mu) * inv * g.y + be.y);
        o2[1] = __floats2bfloat162_rn((v.z - mu) * inv * g.z + be.z,
                                      (v.w - mu) * inv * g.w + be.w);

        int ws = w0 + wl;
        int hd = h - SHIFT;  if (hd < 0) hd += Hdim;
        int wd = ws - SHIFT; if (wd < 0) wd += Wdim;
        int wi = b * NWIMG + (hd / Mwin) * NHw + (wd / Mwin);
        int n  = (hd % Mwin) * Mwin + (wd % Mwin);
        *(uint2*)&g_win[((size_t)wi * Nwin + n) * 128 + c0] = *(uint2*)o2;
    }
}

// ---------------- K2: QKV GEMM (mma.sync bf16) ----------------
#define GQ_SMEM (3 * TILE_B)
__global__ __launch_bounds__(256, 2) void gemm_qkv_kernel(const float* __restrict__ qkv_b) {
    extern __shared__ __align__(16) char sm[];
    char* sA = sm;
    char* sB = sm + TILE_B;
    char* sC = sm + 2 * TILE_B;

    int tid = threadIdx.x, wid = tid >> 5, lane = tid & 31;
    int warp_m = wid >> 2, warp_n = wid & 3;

    const __nv_bfloat16* A = g_win + (size_t)blockIdx.x * (128 * 128);
    for (int e = tid; e < 2048; e += 256) {
        int r = e >> 4, j = e & 15;
        *(uint4*)(sA + r * LDAB + j * 16) = *(const uint4*)(A + r * 128 + j * 8);
    }
    for (int e = tid; e < 2048; e += 256) {
        int r = e >> 4, j = e & 15;
        *(uint4*)(sB + r * LDAB + j * 16) = *(const uint4*)(g_wqkv + r * 128 + j * 8);
    }
    __syncthreads();

    uint32_t pA = smem_u32(sA) + (uint32_t)((warp_m * 64 + (lane & 15)) * LDAB + ((lane >> 4) << 4));
    uint32_t pB = smem_u32(sB) + (uint32_t)((warp_n * 32 + (lane & 15)) * LDAB + ((lane >> 4) << 4));
    size_t row0 = (size_t)blockIdx.x * 128;
    int g = lane >> 2, tg = lane & 3;

    #pragma unroll 1
    for (int jb = 0; jb < 3; ++jb) {
        float c[4][4][4];
        #pragma unroll
        for (int mt = 0; mt < 4; ++mt)
            #pragma unroll
            for (int nt = 0; nt < 4; ++nt)
                #pragma unroll
                for (int q = 0; q < 4; ++q) c[mt][nt][q] = 0.f;

        #pragma unroll
        for (int k0 = 0; k0 < 128; k0 += 16) {
            uint32_t a[4][4], bb[2][4];
            #pragma unroll
            for (int mt = 0; mt < 4; ++mt)
                ldm_x4(a[mt], pA + mt * (16 * LDAB) + k0 * 2);
            #pragma unroll
            for (int p = 0; p < 2; ++p)
                ldm_x4(bb[p], pB + p * (16 * LDAB) + k0 * 2);
            #pragma unroll
            for (int mt = 0; mt < 4; ++mt)
                #pragma unroll
                for (int nt = 0; nt < 4; ++nt)
                    mma_bf16(c[mt][nt], a[mt], bb[nt >> 1][nt & 1], bb[nt >> 1][2 + (nt & 1)]);
        }

        float s = (jb == 0) ? QSCALE : 1.0f;
        #pragma unroll
        for (int nt = 0; nt < 4; ++nt) {
            int col = warp_n * 32 + nt * 8 + 2 * tg;
            float b0v = qkv_b[jb * 128 + col];
            float b1v = qkv_b[jb * 128 + col + 1];
            #pragma unroll
            for (int mt = 0; mt < 4; ++mt) {
                int row = warp_m * 64 + mt * 16 + g;
                __nv_bfloat162 lo = __floats2bfloat162_rn((c[mt][nt][0] + b0v) * s,
                                                          (c[mt][nt][1] + b1v) * s);
                __nv_bfloat162 hi = __floats2bfloat162_rn((c[mt][nt][2] + b0v) * s,
                                                          (c[mt][nt][3] + b1v) * s);
                *(__nv_bfloat162*)(sC + row * LDAB + col * 2) = lo;
                *(__nv_bfloat162*)(sC + (row + 8) * LDAB + col * 2) = hi;
            }
        }
        __syncthreads();

        if (jb < 2) {
            const __nv_bfloat16* Bn = g_wqkv + (size_t)(jb + 1) * 128 * 128;
            for (int e = tid; e < 2048; e += 256) {
                int r = e >> 4, j = e & 15;
                *(uint4*)(sB + r * LDAB + j * 16) = *(const uint4*)(Bn + r * 128 + j * 8);
            }
        }
        for (int e = tid; e < 2048; e += 256) {
            int r = e >> 4, j = e & 15;
            *(uint4*)(g_qkv + (row0 + r) * 384 + jb * 128 + j * 8) =
                *(uint4*)(sC + r * LDAB + j * 16);
        }
        __syncthreads();
    }
}

// ---------------- K3: per-window attention (mma.sync), 2 warps per head ----------------
// CTA = 1 window, 256 threads. warp w: head = w&3, half = w>>2 (m-tiles 2*half..2*half+1)
#define AQK 264
#define AVT 72
#define ATTN_SMEM (64 * AQK * 2 + 128 * AVT * 2)   // 52224 B -> 4 CTAs/SM, 32 warps
__global__ __launch_bounds__(256, 4) void attn_kernel() {
    extern __shared__ __align__(16) __nv_bfloat16 smb[];
    __nv_bfloat16* sQK = smb;
    __nv_bfloat16* sVT = smb + 64 * AQK;

    int wi = blockIdx.x, wimg = wi & (NWIMG - 1), tid = threadIdx.x;
    int wid = tid >> 5, lane = tid & 31;

    const __nv_bfloat16* src = g_qkv + (size_t)wi * Nwin * 384;
    // Q|K rows (cols 0..255), uint4-vectorized
    for (int e = tid; e < Nwin * 32; e += 256) {
        int n = e >> 5, j = e & 31;
        *(uint4*)&sQK[n * AQK + j * 8] = *(const uint4*)(src + n * 384 + j * 8);
    }
    // V transposed: sVT[d][n]
    for (int e = tid; e < Nwin * 16; e += 256) {
        int n = e >> 4, j = e & 15;
        uint4 raw = *(const uint4*)(src + n * 384 + 256 + j * 8);
        __nv_bfloat16 tmp[8]; *(uint4*)tmp = raw;
        #pragma unroll
        for (int q = 0; q < 8; ++q) sVT[(j * 8 + q) * AVT + n] = tmp[q];
    }
    // zero pads: sQK rows 49..63
    for (int e = tid; e < 15 * 33; e += 256) {
        int r = 49 + e / 33, j = e % 33;
        *(uint4*)&sQK[r * AQK + j * 8] = make_uint4(0, 0, 0, 0);
    }
    // zero pads: sVT cols 49..71
    for (int e = tid; e < 128 * 23; e += 256) {
        int d = e / 23, c = 49 + e % 23;
        sVT[d * AVT + c] = __float2bfloat16(0.f);
    }
    __syncthreads();

    int hd = wid & 3, half = wid >> 2;
    int g = lane >> 2, tg = lane & 3;
    uint32_t sqk = smem_u32(sQK), svt = smem_u32(sVT);
    int lrow = lane & 15, lsel = (lane >> 4) << 4;

    // held K fragments: kb[ntp][kt][4]
    uint32_t kb[4][2][4];
    #pragma unroll
    for (int ntp = 0; ntp < 4; ++ntp)
        #pragma unroll
        for (int kt = 0; kt < 2; ++kt)
            ldm_x4(kb[ntp][kt],
                   sqk + (uint32_t)((ntp * 16 + lrow) * (AQK * 2) + (128 + hd * 32 + kt * 16) * 2 + lsel));

    const __nv_bfloat162* cm =
        (const __nv_bfloat162*)(g_cmb + (size_t)(wimg * HEADS + hd) * 64 * 56);
    __nv_bfloat16* dst = g_attn + (size_t)wi * Nwin * 128 + hd * 32;

    #pragma unroll
    for (int mi = 0; mi < 2; ++mi) {
        int mt = half * 2 + mi;
        // Q fragments
        uint32_t qf[2][4];
        #pragma unroll
        for (int kt = 0; kt < 2; ++kt)
            ldm_x4(qf[kt],
                   sqk + (uint32_t)((mt * 16 + lrow) * (AQK * 2) + (hd * 32 + kt * 16) * 2 + lsel));

        int rA = mt * 16 + g, rB = rA + 8;
        // init S accumulators with bias+mask
        float s[7][4];
        #pragma unroll
        for (int nt = 0; nt < 7; ++nt) {
            float2 fa = __bfloat1622float2(cm[(rA * 56 + nt * 8 + 2 * tg) >> 1]);
            float2 fb = __bfloat1622float2(cm[(rB * 56 + nt * 8 + 2 * tg) >> 1]);
            s[nt][0] = fa.x; s[nt][1] = fa.y; s[nt][2] = fb.x; s[nt][3] = fb.y;
        }
        // S = Q K^T (+init)
        #pragma unroll
        for (int kt = 0; kt < 2; ++kt)
            #pragma unroll
            for (int nt = 0; nt < 7; ++nt)
                mma_bf16(s[nt], qf[kt], kb[nt >> 1][kt][nt & 1], kb[nt >> 1][kt][2 + (nt & 1)]);

        // softmax (rows rA: s[nt][0..1], rB: s[nt][2..3]); quad reduce
        float mxA = -1e30f, mxB = -1e30f;
        #pragma unroll
        for (int nt = 0; nt < 7; ++nt) {
            mxA = fmaxf(mxA, fmaxf(s[nt][0], s[nt][1]));
            mxB = fmaxf(mxB, fmaxf(s[nt][2], s[nt][3]));
        }
        mxA = fmaxf(mxA, __shfl_xor_sync(0xffffffff, mxA, 1));
        mxA = fmaxf(mxA, __shfl_xor_sync(0xffffffff, mxA, 2));
        mxB = fmaxf(mxB, __shfl_xor_sync(0xffffffff, mxB, 1));
        mxB = fmaxf(mxB, __shfl_xor_sync(0xffffffff, mxB, 2));
        float sumA = 0.f, sumB = 0.f;
        #pragma unroll
        for (int nt = 0; nt < 7; ++nt) {
            s[nt][0] = __expf(s[nt][0] - mxA); sumA += s[nt][0];
            s[nt][1] = __expf(s[nt][1] - mxA); sumA += s[nt][1];
            s[nt][2] = __expf(s[nt][2] - mxB); sumB += s[nt][2];
            s[nt][3] = __expf(s[nt][3] - mxB); sumB += s[nt][3];
        }
        sumA += __shfl_xor_sync(0xffffffff, sumA, 1);
        sumA += __shfl_xor_sync(0xffffffff, sumA, 2);
        sumB += __shfl_xor_sync(0xffffffff, sumB, 1);
        sumB += __shfl_xor_sync(0xffffffff, sumB, 2);
        float invA = 1.0f / sumA, invB = 1.0f / sumB;
        #pragma unroll
        for (int nt = 0; nt < 7; ++nt) {
            s[nt][0] *= invA; s[nt][1] *= invA;
            s[nt][2] *= invB; s[nt][3] *= invB;
        }

        // pack P into A-fragments (k over token dim; tail zero pad)
        uint32_t pf[4][4];
        #pragma unroll
        for (int kt = 0; kt < 4; ++kt) {
            int nt0 = 2 * kt, nt1 = 2 * kt + 1;
            pf[kt][0] = pack_bf16x2(s[nt0][0], s[nt0][1]);
            pf[kt][1] = pack_bf16x2(s[nt0][2], s[nt0][3]);
            if (nt1 < 7) {
                pf[kt][2] = pack_bf16x2(s[nt1][0], s[nt1][1]);
                pf[kt][3] = pack_bf16x2(s[nt1][2], s[nt1][3]);
            } else {
                pf[kt][2] = 0u; pf[kt][3] = 0u;
            }
        }

        // O = P V
        float o[4][4];
        #pragma unroll
        for (int dt = 0; dt < 4; ++dt)
            #pragma unroll
            for (int q = 0; q < 4; ++q) o[dt][q] = 0.f;
        #pragma unroll
        for (int kt = 0; kt < 4; ++kt) {
            uint32_t vb[2][4];
            #pragma unroll
            for (int dp = 0; dp < 2; ++dp)
                ldm_x4(vb[dp],
                       svt + (uint32_t)((hd * 32 + dp * 16 + lrow) * (AVT * 2) + kt * 32 + lsel));
            #pragma unroll
            for (int dt = 0; dt < 4; ++dt)
                mma_bf16(o[dt], pf[kt], vb[dt >> 1][dt & 1], vb[dt >> 1][2 + (dt & 1)]);
        }

        // store O rows
        int nA = mt * 16 + g, nB = nA + 8;
        #pragma unroll
        for (int dt = 0; dt < 4; ++dt) {
            int col = dt * 8 + 2 * tg;
            if (nA < Nwin) {
                __nv_bfloat162 v = __floats2bfloat162_rn(o[dt][0], o[dt][1]);
                *(__nv_bfloat162*)&dst[(size_t)nA * 128 + col] = v;
            }
            if (nB < Nwin) {
                __nv_bfloat162 v = __floats2bfloat162_rn(o[dt][2], o[dt][3]);
                *(__nv_bfloat162*)&dst[(size_t)nB * 128 + col] = v;
            }
        }
    }
}

// ---------------- K4: proj GEMM (mma.sync bf16), bf16 output ----------------
#define GP_SMEM (2 * TILE_B)
__global__ __launch_bounds__(256, 2) void gemm_proj_kernel(const float* __restrict__ proj_b) {
    extern __shared__ __align__(16) char sm[];
    char* sA = sm;
    char* sB = sm + TILE_B;

    int tid = threadIdx.x, wid = tid >> 5, lane = tid & 31;
    int warp_m = wid >> 2, warp_n = wid & 3;

    const __nv_bfloat16* A = g_attn + (size_t)blockIdx.x * (128 * 128);
    for (int e = tid; e < 2048; e += 256) {
        int r = e >> 4, j = e & 15;
        *(uint4*)(sA + r * LDAB + j * 16) = *(const uint4*)(A + r * 128 + j * 8);
    }
    for (int e = tid; e < 2048; e += 256) {
        int r = e >> 4, j = e & 15;
        *(uint4*)(sB + r * LDAB + j * 16) = *(const uint4*)(g_wproj + r * 128 + j * 8);
    }
    __syncthreads();

    uint32_t pA = smem_u32(sA) + (uint32_t)((warp_m * 64 + (lane & 15)) * LDAB + ((lane >> 4) << 4));
    uint32_t pB = smem_u32(sB) + (uint32_t)((warp_n * 32 + (lane & 15)) * LDAB + ((lane >> 4) << 4));

    float c[4][4][4];
    #pragma unroll
    for (int mt = 0; mt < 4; ++mt)
        #pragma unroll
        for (int nt = 0; nt < 4; ++nt)
            #pragma unroll
            for (int q = 0; q < 4; ++q) c[mt][nt][q] = 0.f;

    #pragma unroll
    for (int k0 = 0; k0 < 128; k0 += 16) {
        uint32_t a[4][4], bb[2][4];
        #pragma unroll
        for (int mt = 0; mt < 4; ++mt)
            ldm_x4(a[mt], pA + mt * (16 * LDAB) + k0 * 2);
        #pragma unroll
        for (int p = 0; p < 2; ++p)
            ldm_x4(bb[p], pB + p * (16 * LDAB) + k0 * 2);
        #pragma unroll
        for (int mt = 0; mt < 4; ++mt)
            #pragma unroll
            for (int nt = 0; nt < 4; ++nt)
                mma_bf16(c[mt][nt], a[mt], bb[nt >> 1][nt & 1], bb[nt >> 1][2 + (nt & 1)]);
    }
    __syncthreads();   // before overwriting sA/sB with the bf16 stage

    __nv_bfloat16* sCb = (__nv_bfloat16*)sm;   // [128][136] bf16
    int g = lane >> 2, tg = lane & 3;
    #pragma unroll
    for (int nt = 0; nt < 4; ++nt) {
        int col = warp_n * 32 + nt * 8 + 2 * tg;
        float b0v = proj_b[col], b1v = proj_b[col + 1];
        #pragma unroll
        for (int mt = 0; mt < 4; ++mt) {
            int row = warp_m * 64 + mt * 16 + g;
            *(__nv_bfloat162*)&sCb[row * 136 + col] =
                __floats2bfloat162_rn(c[mt][nt][0] + b0v, c[mt][nt][1] + b1v);
            *(__nv_bfloat162*)&sCb[(row + 8) * 136 + col] =
                __floats2bfloat162_rn(c[mt][nt][2] + b0v, c[mt][nt][3] + b1v);
        }
    }
    __syncthreads();

    size_t row0 = (size_t)blockIdx.x * 128;
    for (int e = tid; e < 2048; e += 256) {
        int r = e >> 4, j = e & 15;
        *(uint4*)(g_owin + (row0 + r) * 128 + j * 8) = *(uint4*)&sCb[r * 136 + j * 8];
    }
}

// ---------------- K5: window reverse + unshift + residual ----------------
__global__ void reverse_kernel(const float* __restrict__ x,
                               float* __restrict__ out) {
    __shared__ float s[128 * 57];
    int h = blockIdx.x, half = blockIdx.y, b = blockIdx.z;
    int w0 = half * 56;
    int tid = threadIdx.x;

    int h2 = h - SHIFT; if (h2 < 0) h2 += Hdim;
    int whh = h2 / Mwin, rr = h2 % Mwin;

    for (int e = tid; e < 56 * 128; e += 256) {
        int wl = e >> 7, c = e & 127;
        int w = w0 + wl;
        int w2 = w - SHIFT; if (w2 < 0) w2 += Wdim;
        int wi = b * NWIMG + whh * NHw + (w2 / Mwin);
        int n  = rr * Mwin + (w2 % Mwin);
        s[c * 57 + wl] = __bfloat162float(g_owin[((size_t)wi * Nwin + n) * 128 + c]);
    }
    __syncthreads();

    size_t base = (size_t)b * Cdim * (Hdim * Wdim) + (size_t)h * Wdim + w0;
    for (int e = tid; e < 128 * 56; e += 256) {
        int c = e / 56, wl = e % 56;
        size_t gi = base + (size_t)c * (Hdim * Wdim) + wl;
        out[gi] = x[gi] + s[c * 57 + wl];
    }
}

// ---------------- launch ----------------
extern "C" void kernel_launch(void* const* d_in, const int* in_sizes, int n_in,
                              void* d_out, int out_size) {
    const float* x          = (const float*)d_in[0];
    const float* norm_w     = (const float*)d_in[1];
    const float* norm_b     = (const float*)d_in[2];
    const float* qkv_w      = (const float*)d_in[3];
    const float* qkv_b      = (const float*)d_in[4];
    const float* proj_w     = (const float*)d_in[5];
    const float* proj_b     = (const float*)d_in[6];
    const float* bias_table = (const float*)d_in[7];
    const int*   rel_index  = (const int*)  d_in[8];
    const float* attn_mask  = (const float*)d_in[9];
    float* out = (float*)d_out;

    cudaFuncSetAttribute(gemm_qkv_kernel,  cudaFuncAttributeMaxDynamicSharedMemorySize, GQ_SMEM);
    cudaFuncSetAttribute(gemm_proj_kernel, cudaFuncAttributeMaxDynamicSharedMemorySize, GP_SMEM);
    cudaFuncSetAttribute(attn_kernel,      cudaFuncAttributeMaxDynamicSharedMemorySize, ATTN_SMEM);

    int prep_total = 384 * 128 + 128 * 128 + HEADS * Nwin * Nwin;
    prep_kernel<<<(prep_total + 255) / 256, 256>>>(qkv_w, proj_w, bias_table, rel_index);
    int cmb_total = NWIMG * HEADS * 64 * 56;
    cmb_kernel<<<(cmb_total + 255) / 256, 256>>>(attn_mask);
    ln_window_kernel<<<dim3(Hdim, 2, Bsz), 256>>>(x, norm_w, norm_b);
    gemm_qkv_kernel<<<NTOK / 128, 256, GQ_SMEM>>>(qkv_b);
    attn_kernel<<<NWTOT, 256, ATTN_SMEM>>>();
    gemm_proj_kernel<<<NTOK / 128, 256, GP_SMEM>>>(proj_b);
    reverse_kernel<<<dim3(Hdim, 2, Bsz), 256>>>(x, out);
}

// round 6
// speedup vs baseline: 7.5741x; 1.0588x over previous
#include <cuda_runtime.h>
#include <cuda_bf16.h>
#include <cstdint>

#define Bsz   32
#define Cdim  128
#define Hdim  112
#define Wdim  112
#define Mwin  7
#define Nwin  49
#define NHw   16
#define NWIMG 256
#define NWTOT 8192
#define HEADS 4
#define DHEAD 32
#define SHIFT 3
#define NTOK  (NWTOT * Nwin)          // 401408
#define QSCALE 0.17677669529663687f   // 1/sqrt(32)

// ---------------- scratch (device globals; no allocation) ----------------
__device__ __nv_bfloat16 g_win [(size_t)NTOK * 128];   // LN+shifted tokens (bf16)
__device__ __nv_bfloat16 g_qkv [(size_t)NTOK * 384];   // QKV (bf16, Q pre-scaled)
__device__ __nv_bfloat16 g_attn[(size_t)NTOK * 128];   // attention output (bf16)
__device__ __nv_bfloat16 g_owin[(size_t)NTOK * 128];   // proj output (bf16, bias added)
__device__ __nv_bfloat16 g_wqkv [384 * 128];           // bf16 weights [j][k]
__device__ __nv_bfloat16 g_wproj[128 * 128];
__device__ float         g_bias [HEADS * Nwin * Nwin];
__device__ __nv_bfloat16 g_cmb  [(size_t)NWIMG * HEADS * 64 * 56];  // bias+mask combined

// ---------------- helpers ----------------
__device__ __forceinline__ uint32_t smem_u32(const void* p) {
    uint32_t a;
    asm("{ .reg .u64 t; cvta.to.shared.u64 t, %1; cvt.u32.u64 %0, t; }" : "=r"(a) : "l"(p));
    return a;
}
__device__ __forceinline__ void ldm_x4(uint32_t r[4], uint32_t addr) {
    asm volatile("ldmatrix.sync.aligned.m8n8.x4.shared.b16 {%0,%1,%2,%3}, [%4];"
        : "=r"(r[0]), "=r"(r[1]), "=r"(r[2]), "=r"(r[3]) : "r"(addr));
}
__device__ __forceinline__ void ldm_x4_t(uint32_t r[4], uint32_t addr) {
    asm volatile("ldmatrix.sync.aligned.m8n8.x4.trans.shared.b16 {%0,%1,%2,%3}, [%4];"
        : "=r"(r[0]), "=r"(r[1]), "=r"(r[2]), "=r"(r[3]) : "r"(addr));
}
__device__ __forceinline__ void mma_bf16(float c[4], const uint32_t a[4],
                                         uint32_t b0, uint32_t b1) {
    asm volatile("mma.sync.aligned.m16n8k16.row.col.f32.bf16.bf16.f32 "
        "{%0,%1,%2,%3}, {%4,%5,%6,%7}, {%8,%9}, {%0,%1,%2,%3};"
        : "+f"(c[0]), "+f"(c[1]), "+f"(c[2]), "+f"(c[3])
        : "r"(a[0]), "r"(a[1]), "r"(a[2]), "r"(a[3]), "r"(b0), "r"(b1));
}
__device__ __forceinline__ uint32_t pack_bf16x2(float a, float b) {
    __nv_bfloat162 t = __floats2bfloat162_rn(a, b);
    return *(uint32_t*)&t;
}

#define LDAB 272          // GEMM smem row stride in bytes (136 bf16)
#define TILE_B 34816      // 128 * 272

// ---------------- K0: weight bf16 conversion + bias gather ----------------
__global__ void prep_kernel(const float* __restrict__ qkv_w,
                            const float* __restrict__ proj_w,
                            const float* __restrict__ bias_table,
                            const int*   __restrict__ rel_index) {
    int i = blockIdx.x * blockDim.x + threadIdx.x;
    if (i < 384 * 128) {
        g_wqkv[i] = __float2bfloat16_rn(qkv_w[i]);
    } else if (i < 384 * 128 + 128 * 128) {
        int t = i - 384 * 128;
        g_wproj[t] = __float2bfloat16_rn(proj_w[t]);
    } else if (i < 384 * 128 + 128 * 128 + HEADS * Nwin * Nwin) {
        int t = i - (384 * 128 + 128 * 128);
        int hd = t / (Nwin * Nwin), nm = t % (Nwin * Nwin);
        g_bias[t] = bias_table[rel_index[nm] * HEADS + hd];
    }
}

// ---------------- K0b: combined bias+mask (bf16), padded to [64][56] ----------------
__global__ void cmb_kernel(const float* __restrict__ attn_mask) {
    int i = blockIdx.x * blockDim.x + threadIdx.x;
    if (i >= NWIMG * HEADS * 64 * 56) return;
    int m = i % 56; int t = i / 56;
    int n = t & 63; t >>= 6;
    int hd = t & 3; int wimg = t >> 2;
    float v;
    if (n >= Nwin)      v = 0.f;
    else if (m >= Nwin) v = -30000.f;
    else v = g_bias[hd * (Nwin * Nwin) + n * Nwin + m]
           + attn_mask[((size_t)wimg * Nwin + n) * Nwin + m];
    g_cmb[i] = __float2bfloat16_rn(v);
}

// ---------------- K1: LayerNorm + shift + window partition (bf16 out) ----------------
#define RS 132
__global__ void ln_window_kernel(const float* __restrict__ x,
                                 const float* __restrict__ nw,
                                 const float* __restrict__ nb) {
    __shared__ float s[56 * RS];
    int h = blockIdx.x, half = blockIdx.y, b = blockIdx.z;
    int w0 = half * 56;
    int tid = threadIdx.x;

    const float* xp = x + (size_t)b * Cdim * (Hdim * Wdim) + (size_t)h * Wdim + w0;
    for (int e = tid; e < 56 * 128; e += 256) {
        int c = e / 56, w = e % 56;
        s[w * RS + c] = xp[(size_t)c * (Hdim * Wdim) + w];
    }
    __syncthreads();

    int warp = tid >> 5, lane = tid & 31;
    for (int wl = warp; wl < 56; wl += 8) {
        float4 v = *(const float4*)&s[wl * RS + lane * 4];
        float sum = v.x + v.y + v.z + v.w;
        float sq  = v.x * v.x + v.y * v.y + v.z * v.z + v.w * v.w;
        #pragma unroll
        for (int o = 16; o > 0; o >>= 1) {
            sum += __shfl_xor_sync(0xffffffff, sum, o);
            sq  += __shfl_xor_sync(0xffffffff, sq,  o);
        }
        float mu  = sum * (1.0f / 128.0f);
        float var = sq * (1.0f / 128.0f) - mu * mu;
        float inv = rsqrtf(var + 1e-5f);

        int c0 = lane * 4;
        float4 g  = *(const float4*)&nw[c0];
        float4 be = *(const float4*)&nb[c0];
        __align__(8) __nv_bfloat162 o2[2];
        o2[0] = __floats2bfloat162_rn((v.x - mu) * inv * g.x + be.x,
                                      (v.y - mu) * inv * g.y + be.y);
        o2[1] = __floats2bfloat162_rn((v.z - mu) * inv * g.z + be.z,
                                      (v.w - mu) * inv * g.w + be.w);

        int ws = w0 + wl;
        int hd = h - SHIFT;  if (hd < 0) hd += Hdim;
        int wd = ws - SHIFT; if (wd < 0) wd += Wdim;
        int wi = b * NWIMG + (hd / Mwin) * NHw + (wd / Mwin);
        int n  = (hd % Mwin) * Mwin + (wd % Mwin);
        *(uint2*)&g_win[((size_t)wi * Nwin + n) * 128 + c0] = *(uint2*)o2;
    }
}

// ---------------- K2: QKV GEMM (mma.sync bf16) ----------------
#define GQ_SMEM (3 * TILE_B)
__global__ __launch_bounds__(256, 2) void gemm_qkv_kernel(const float* __restrict__ qkv_b) {
    extern __shared__ __align__(16) char sm[];
    char* sA = sm;
    char* sB = sm + TILE_B;
    char* sC = sm + 2 * TILE_B;

    int tid = threadIdx.x, wid = tid >> 5, lane = tid & 31;
    int warp_m = wid >> 2, warp_n = wid & 3;

    const __nv_bfloat16* A = g_win + (size_t)blockIdx.x * (128 * 128);
    for (int e = tid; e < 2048; e += 256) {
        int r = e >> 4, j = e & 15;
        *(uint4*)(sA + r * LDAB + j * 16) = *(const uint4*)(A + r * 128 + j * 8);
    }
    for (int e = tid; e < 2048; e += 256) {
        int r = e >> 4, j = e & 15;
        *(uint4*)(sB + r * LDAB + j * 16) = *(const uint4*)(g_wqkv + r * 128 + j * 8);
    }
    __syncthreads();

    uint32_t pA = smem_u32(sA) + (uint32_t)((warp_m * 64 + (lane & 15)) * LDAB + ((lane >> 4) << 4));
    uint32_t pB = smem_u32(sB) + (uint32_t)((warp_n * 32 + (lane & 15)) * LDAB + ((lane >> 4) << 4));
    size_t row0 = (size_t)blockIdx.x * 128;
    int g = lane >> 2, tg = lane & 3;

    #pragma unroll 1
    for (int jb = 0; jb < 3; ++jb) {
        float c[4][4][4];
        #pragma unroll
        for (int mt = 0; mt < 4; ++mt)
            #pragma unroll
            for (int nt = 0; nt < 4; ++nt)
                #pragma unroll
                for (int q = 0; q < 4; ++q) c[mt][nt][q] = 0.f;

        #pragma unroll
        for (int k0 = 0; k0 < 128; k0 += 16) {
            uint32_t a[4][4], bb[2][4];
            #pragma unroll
            for (int mt = 0; mt < 4; ++mt)
                ldm_x4(a[mt], pA + mt * (16 * LDAB) + k0 * 2);
            #pragma unroll
            for (int p = 0; p < 2; ++p)
                ldm_x4(bb[p], pB + p * (16 * LDAB) + k0 * 2);
            #pragma unroll
            for (int mt = 0; mt < 4; ++mt)
                #pragma unroll
                for (int nt = 0; nt < 4; ++nt)
                    mma_bf16(c[mt][nt], a[mt], bb[nt >> 1][nt & 1], bb[nt >> 1][2 + (nt & 1)]);
        }

        float s = (jb == 0) ? QSCALE : 1.0f;
        #pragma unroll
        for (int nt = 0; nt < 4; ++nt) {
            int col = warp_n * 32 + nt * 8 + 2 * tg;
            float b0v = qkv_b[jb * 128 + col];
            float b1v = qkv_b[jb * 128 + col + 1];
            #pragma unroll
            for (int mt = 0; mt < 4; ++mt) {
                int row = warp_m * 64 + mt * 16 + g;
                __nv_bfloat162 lo = __floats2bfloat162_rn((c[mt][nt][0] + b0v) * s,
                                                          (c[mt][nt][1] + b1v) * s);
                __nv_bfloat162 hi = __floats2bfloat162_rn((c[mt][nt][2] + b0v) * s,
                                                          (c[mt][nt][3] + b1v) * s);
                *(__nv_bfloat162*)(sC + row * LDAB + col * 2) = lo;
                *(__nv_bfloat162*)(sC + (row + 8) * LDAB + col * 2) = hi;
            }
        }
        __syncthreads();

        if (jb < 2) {
            const __nv_bfloat16* Bn = g_wqkv + (size_t)(jb + 1) * 128 * 128;
            for (int e = tid; e < 2048; e += 256) {
                int r = e >> 4, j = e & 15;
                *(uint4*)(sB + r * LDAB + j * 16) = *(const uint4*)(Bn + r * 128 + j * 8);
            }
        }
        for (int e = tid; e < 2048; e += 256) {
            int r = e >> 4, j = e & 15;
            *(uint4*)(g_qkv + (row0 + r) * 384 + jb * 128 + j * 8) =
                *(uint4*)(sC + r * LDAB + j * 16);
        }
        __syncthreads();
    }
}

// ---------------- K3: per-window attention (mma.sync), 2 warps per head ----------------
// CTA = 1 window, 256 threads. warp w: head = w&3, half = w>>2.
// smem: sQKV [64][392] bf16 (row 784B, ldmatrix conflict-free); V via ldmatrix.trans
#define AQKV 392
#define ATTN_SMEM (64 * AQKV * 2)   // 50176 B -> 3 CTAs/SM (smem), 24 warps
__global__ __launch_bounds__(256, 3) void attn_kernel() {
    extern __shared__ __align__(16) __nv_bfloat16 smb[];
    __nv_bfloat16* sQKV = smb;

    int wi = blockIdx.x, wimg = wi & (NWIMG - 1), tid = threadIdx.x;
    int wid = tid >> 5, lane = tid & 31;

    const __nv_bfloat16* src = g_qkv + (size_t)wi * Nwin * 384;
    // rows 0..48: copy Q|K|V (384 cols) as 48 uint4 per row
    for (int e = tid; e < Nwin * 48; e += 256) {
        int n = e / 48, j = e % 48;
        *(uint4*)&sQKV[n * AQKV + j * 8] = *(const uint4*)(src + n * 384 + j * 8);
    }
    // rows 49..63: zero (full 392-col rows = 49 uint4)
    for (int e = tid; e < 15 * 49; e += 256) {
        int r = 49 + e / 49, j = e % 49;
        *(uint4*)&sQKV[r * AQKV + j * 8] = make_uint4(0, 0, 0, 0);
    }
    __syncthreads();

    int hd = wid & 3, half = wid >> 2;
    int g = lane >> 2, tg = lane & 3;
    uint32_t sq = smem_u32(sQKV);
    int lrow = lane & 15, lsel = (lane >> 4) << 4;
    // per-fragment base addrs (row = lrow within tile, col-halves via lsel)
    uint32_t baseQ = sq + (uint32_t)(lrow * (AQKV * 2) + (hd * 32) * 2 + lsel);
    uint32_t baseK = sq + (uint32_t)(lrow * (AQKV * 2) + (128 + hd * 32) * 2 + lsel);
    uint32_t baseV = sq + (uint32_t)(lrow * (AQKV * 2) + (256 + hd * 32) * 2 + lsel);

    const __nv_bfloat162* cm =
        (const __nv_bfloat162*)(g_cmb + (size_t)(wimg * HEADS + hd) * 64 * 56);
    __nv_bfloat16* dst = g_attn + (size_t)wi * Nwin * 128 + hd * 32;

    #pragma unroll
    for (int mi = 0; mi < 2; ++mi) {
        int mt = half * 2 + mi;
        // Q fragments (A operand)
        uint32_t qf[2][4];
        #pragma unroll
        for (int kt = 0; kt < 2; ++kt)
            ldm_x4(qf[kt], baseQ + (uint32_t)(mt * 16 * (AQKV * 2) + kt * 32));

        int rA = mt * 16 + g, rB = rA + 8;
        // init S accumulators with bias+mask
        float s[7][4];
        #pragma unroll
        for (int nt = 0; nt < 7; ++nt) {
            float2 fa = __bfloat1622float2(cm[(rA * 56 + nt * 8 + 2 * tg) >> 1]);
            float2 fb = __bfloat1622float2(cm[(rB * 56 + nt * 8 + 2 * tg) >> 1]);
            s[nt][0] = fa.x; s[nt][1] = fa.y; s[nt][2] = fb.x; s[nt][3] = fb.y;
        }
        // S = Q K^T (+init); K fragments transient
        #pragma unroll
        for (int kt = 0; kt < 2; ++kt) {
            #pragma unroll
            for (int ntp = 0; ntp < 4; ++ntp) {
                uint32_t kb[4];
                ldm_x4(kb, baseK + (uint32_t)(ntp * 16 * (AQKV * 2) + kt * 32));
                mma_bf16(s[2 * ntp], qf[kt], kb[0], kb[2]);
                if (ntp < 3) mma_bf16(s[2 * ntp + 1], qf[kt], kb[1], kb[3]);
            }
        }

        // softmax (rows rA: s[nt][0..1], rB: s[nt][2..3]); quad reduce
        float mxA = -1e30f, mxB = -1e30f;
        #pragma unroll
        for (int nt = 0; nt < 7; ++nt) {
            mxA = fmaxf(mxA, fmaxf(s[nt][0], s[nt][1]));
            mxB = fmaxf(mxB, fmaxf(s[nt][2], s[nt][3]));
        }
        mxA = fmaxf(mxA, __shfl_xor_sync(0xffffffff, mxA, 1));
        mxA = fmaxf(mxA, __shfl_xor_sync(0xffffffff, mxA, 2));
        mxB = fmaxf(mxB, __shfl_xor_sync(0xffffffff, mxB, 1));
        mxB = fmaxf(mxB, __shfl_xor_sync(0xffffffff, mxB, 2));
        float sumA = 0.f, sumB = 0.f;
        #pragma unroll
        for (int nt = 0; nt < 7; ++nt) {
            s[nt][0] = __expf(s[nt][0] - mxA); sumA += s[nt][0];
            s[nt][1] = __expf(s[nt][1] - mxA); sumA += s[nt][1];
            s[nt][2] = __expf(s[nt][2] - mxB); sumB += s[nt][2];
            s[nt][3] = __expf(s[nt][3] - mxB); sumB += s[nt][3];
        }
        sumA += __shfl_xor_sync(0xffffffff, sumA, 1);
        sumA += __shfl_xor_sync(0xffffffff, sumA, 2);
        sumB += __shfl_xor_sync(0xffffffff, sumB, 1);
        sumB += __shfl_xor_sync(0xffffffff, sumB, 2);
        float invA = 1.0f / sumA, invB = 1.0f / sumB;
        #pragma unroll
        for (int nt = 0; nt < 7; ++nt) {
            s[nt][0] *= invA; s[nt][1] *= invA;
            s[nt][2] *= invB; s[nt][3] *= invB;
        }

        // pack P into A-fragments (k over token dim; tail zero pad)
        uint32_t pf[4][4];
        #pragma unroll
        for (int kt = 0; kt < 4; ++kt) {
            int nt0 = 2 * kt, nt1 = 2 * kt + 1;
            pf[kt][0] = pack_bf16x2(s[nt0][0], s[nt0][1]);
            pf[kt][1] = pack_bf16x2(s[nt0][2], s[nt0][3]);
            if (nt1 < 7) {
                pf[kt][2] = pack_bf16x2(s[nt1][0], s[nt1][1]);
                pf[kt][3] = pack_bf16x2(s[nt1][2], s[nt1][3]);
            } else {
                pf[kt][2] = 0u; pf[kt][3] = 0u;
            }
        }

        // O = P V ; V B-fragments via ldmatrix.trans (V stored row-major [tok][d])
        float o[4][4];
        #pragma unroll
        for (int dt = 0; dt < 4; ++dt)
            #pragma unroll
            for (int q = 0; q < 4; ++q) o[dt][q] = 0.f;
        #pragma unroll
        for (int kt = 0; kt < 4; ++kt) {
            uint32_t vb[2][4];
            #pragma unroll
            for (int dp = 0; dp < 2; ++dp)
                ldm_x4_t(vb[dp], baseV + (uint32_t)(kt * 16 * (AQKV * 2) + dp * 32));
            #pragma unroll
            for (int dt = 0; dt < 4; ++dt)
                mma_bf16(o[dt], pf[kt], vb[dt >> 1][2 * (dt & 1)], vb[dt >> 1][2 * (dt & 1) + 1]);
        }

        // store O rows
        int nA = mt * 16 + g, nB = nA + 8;
        #pragma unroll
        for (int dt = 0; dt < 4; ++dt) {
            int col = dt * 8 + 2 * tg;
            if (nA < Nwin) {
                __nv_bfloat162 v = __floats2bfloat162_rn(o[dt][0], o[dt][1]);
                *(__nv_bfloat162*)&dst[(size_t)nA * 128 + col] = v;
            }
            if (nB < Nwin) {
                __nv_bfloat162 v = __floats2bfloat162_rn(o[dt][2], o[dt][3]);
                *(__nv_bfloat162*)&dst[(size_t)nB * 128 + col] = v;
            }
        }
    }
}

// ---------------- K4: proj GEMM (mma.sync bf16), bf16 output ----------------
#define GP_SMEM (2 * TILE_B)
__global__ __launch_bounds__(256, 2) void gemm_proj_kernel(const float* __restrict__ proj_b) {
    extern __shared__ __align__(16) char sm[];
    char* sA = sm;
    char* sB = sm + TILE_B;

    int tid = threadIdx.x, wid = tid >> 5, lane = tid & 31;
    int warp_m = wid >> 2, warp_n = wid & 3;

    const __nv_bfloat16* A = g_attn + (size_t)blockIdx.x * (128 * 128);
    for (int e = tid; e < 2048; e += 256) {
        int r = e >> 4, j = e & 15;
        *(uint4*)(sA + r * LDAB + j * 16) = *(const uint4*)(A + r * 128 + j * 8);
    }
    for (int e = tid; e < 2048; e += 256) {
        int r = e >> 4, j = e & 15;
        *(uint4*)(sB + r * LDAB + j * 16) = *(const uint4*)(g_wproj + r * 128 + j * 8);
    }
    __syncthreads();

    uint32_t pA = smem_u32(sA) + (uint32_t)((warp_m * 64 + (lane & 15)) * LDAB + ((lane >> 4) << 4));
    uint32_t pB = smem_u32(sB) + (uint32_t)((warp_n * 32 + (lane & 15)) * LDAB + ((lane >> 4) << 4));

    float c[4][4][4];
    #pragma unroll
    for (int mt = 0; mt < 4; ++mt)
        #pragma unroll
        for (int nt = 0; nt < 4; ++nt)
            #pragma unroll
            for (int q = 0; q < 4; ++q) c[mt][nt][q] = 0.f;

    #pragma unroll
    for (int k0 = 0; k0 < 128; k0 += 16) {
        uint32_t a[4][4], bb[2][4];
        #pragma unroll
        for (int mt = 0; mt < 4; ++mt)
            ldm_x4(a[mt], pA + mt * (16 * LDAB) + k0 * 2);
        #pragma unroll
        for (int p = 0; p < 2; ++p)
            ldm_x4(bb[p], pB + p * (16 * LDAB) + k0 * 2);
        #pragma unroll
        for (int mt = 0; mt < 4; ++mt)
            #pragma unroll
            for (int nt = 0; nt < 4; ++nt)
                mma_bf16(c[mt][nt], a[mt], bb[nt >> 1][nt & 1], bb[nt >> 1][2 + (nt & 1)]);
    }
    __syncthreads();   // before overwriting sA/sB with the bf16 stage

    __nv_bfloat16* sCb = (__nv_bfloat16*)sm;   // [128][136] bf16
    int g = lane >> 2, tg = lane & 3;
    #pragma unroll
    for (int nt = 0; nt < 4; ++nt) {
        int col = warp_n * 32 + nt * 8 + 2 * tg;
        float b0v = proj_b[col], b1v = proj_b[col + 1];
        #pragma unroll
        for (int mt = 0; mt < 4; ++mt) {
            int row = warp_m * 64 + mt * 16 + g;
            *(__nv_bfloat162*)&sCb[row * 136 + col] =
                __floats2bfloat162_rn(c[mt][nt][0] + b0v, c[mt][nt][1] + b1v);
            *(__nv_bfloat162*)&sCb[(row + 8) * 136 + col] =
                __floats2bfloat162_rn(c[mt][nt][2] + b0v, c[mt][nt][3] + b1v);
        }
    }
    __syncthreads();

    size_t row0 = (size_t)blockIdx.x * 128;
    for (int e = tid; e < 2048; e += 256) {
        int r = e >> 4, j = e & 15;
        *(uint4*)(g_owin + (row0 + r) * 128 + j * 8) = *(uint4*)&sCb[r * 136 + j * 8];
    }
}

// ---------------- K5: window reverse + unshift + residual ----------------
__global__ void reverse_kernel(const float* __restrict__ x,
                               float* __restrict__ out) {
    __shared__ float s[128 * 57];
    int h = blockIdx.x, half = blockIdx.y, b = blockIdx.z;
    int w0 = half * 56;
    int tid = threadIdx.x;

    int h2 = h - SHIFT; if (h2 < 0) h2 += Hdim;
    int whh = h2 / Mwin, rr = h2 % Mwin;

    for (int e = tid; e < 56 * 128; e += 256) {
        int wl = e >> 7, c = e & 127;
        int w = w0 + wl;
        int w2 = w - SHIFT; if (w2 < 0) w2 += Wdim;
        int wi = b * NWIMG + whh * NHw + (w2 / Mwin);
        int n  = rr * Mwin + (w2 % Mwin);
        s[c * 57 + wl] = __bfloat162float(g_owin[((size_t)wi * Nwin + n) * 128 + c]);
    }
    __syncthreads();

    size_t base = (size_t)b * Cdim * (Hdim * Wdim) + (size_t)h * Wdim + w0;
    for (int e = tid; e < 128 * 56; e += 256) {
        int c = e / 56, wl = e % 56;
        size_t gi = base + (size_t)c * (Hdim * Wdim) + wl;
        out[gi] = x[gi] + s[c * 57 + wl];
    }
}

// ---------------- launch ----------------
extern "C" void kernel_launch(void* const* d_in, const int* in_sizes, int n_in,
                              void* d_out, int out_size) {
    const float* x          = (const float*)d_in[0];
    const float* norm_w     = (const float*)d_in[1];
    const float* norm_b     = (const float*)d_in[2];
    const float* qkv_w      = (const float*)d_in[3];
    const float* qkv_b      = (const float*)d_in[4];
    const float* proj_w     = (const float*)d_in[5];
    const float* proj_b     = (const float*)d_in[6];
    const float* bias_table = (const float*)d_in[7];
    const int*   rel_index  = (const int*)  d_in[8];
    const float* attn_mask  = (const float*)d_in[9];
    float* out = (float*)d_out;

    cudaFuncSetAttribute(gemm_qkv_kernel,  cudaFuncAttributeMaxDynamicSharedMemorySize, GQ_SMEM);
    cudaFuncSetAttribute(gemm_proj_kernel, cudaFuncAttributeMaxDynamicSharedMemorySize, GP_SMEM);
    cudaFuncSetAttribute(attn_kernel,      cudaFuncAttributeMaxDynamicSharedMemorySize, ATTN_SMEM);

    int prep_total = 384 * 128 + 128 * 128 + HEADS * Nwin * Nwin;
    prep_kernel<<<(prep_total + 255) / 256, 256>>>(qkv_w, proj_w, bias_table, rel_index);
    int cmb_total = NWIMG * HEADS * 64 * 56;
    cmb_kernel<<<(cmb_total + 255) / 256, 256>>>(attn_mask);
    ln_window_kernel<<<dim3(Hdim, 2, Bsz), 256>>>(x, norm_w, norm_b);
    gemm_qkv_kernel<<<NTOK / 128, 256, GQ_SMEM>>>(qkv_b);
    attn_kernel<<<NWTOT, 256, ATTN_SMEM>>>();
    gemm_proj_kernel<<<NTOK / 128, 256, GP_SMEM>>>(proj_b);
    reverse_kernel<<<dim3(Hdim, 2, Bsz), 256>>>(x, out);
}